// round 9
// baseline (speedup 1.0000x reference)
#include <cuda_runtime.h>
#include <cuda_fp16.h>
#include <cstdint>

#define BB   16
#define CIN  512
#define HH   40
#define WW   40
#define HW   1600
#define NTOK 80
#define CG   512
#define EE   256
#define COUT 512
#define NH   8
#define HC   32
#define BN_EPS 1e-3f
// 41-stride shared-pad pixel space: pi = r*41 + c, slot c=40 of each row = shared pad
#define PBUF 1792
#define XOFF 64

// ------------------------------ scratch (device globals) -------------------
__device__ float g_buf[BB * NTOK * EE];
__device__ float attn_buf[BB * NH * HW];
__device__ __align__(256) __half xp_hi[(size_t)BB * PBUF * CIN];
__device__ __align__(256) __half wk_h[(size_t)9 * COUT * CIN];
__device__ __align__(256) __half we_h[EE * CIN];

// ------------------------------ helpers ------------------------------------
__device__ __forceinline__ uint32_t smem_u32(const void* p) {
    uint32_t a;
    asm("{ .reg .u64 t; cvta.to.shared.u64 t, %1; cvt.u32.u64 %0, t; }" : "=r"(a) : "l"(p));
    return a;
}
#define SW128(off) ((off) ^ (((off) >> 3) & 0x70))

__device__ __forceinline__ void cp16(uint32_t dst, const void* src) {
    asm volatile("cp.async.cg.shared.global [%0], [%1], 16;" :: "r"(dst), "l"(src));
}

#define LDSM_X4(r, a) \
    asm volatile("ldmatrix.sync.aligned.m8n8.x4.shared.b16 {%0,%1,%2,%3}, [%4];" \
        : "=r"((r)[0]), "=r"((r)[1]), "=r"((r)[2]), "=r"((r)[3]) : "r"(a))

#define MMA16816(d, a, b0, b1) \
    asm volatile("mma.sync.aligned.m16n8k16.row.col.f32.f16.f16.f32 " \
        "{%0,%1,%2,%3}, {%4,%5,%6,%7}, {%8,%9}, {%0,%1,%2,%3};" \
        : "+f"((d)[0]), "+f"((d)[1]), "+f"((d)[2]), "+f"((d)[3]) \
        : "r"((a)[0]), "r"((a)[1]), "r"((a)[2]), "r"((a)[3]), "r"(b0), "r"(b1))

// ---------------- Kernel 1: guide FC  g = guide @ Wg^T + bg ----------------
__global__ void guide_gemm(const float* __restrict__ guide,
                           const float* __restrict__ Wg,
                           const float* __restrict__ bg) {
    __shared__ float As[32][33];
    __shared__ float Bs[32][33];
    int tid  = threadIdx.x;
    int row0 = blockIdx.x * 32;
    int col0 = blockIdx.y * 32;
    int tx = tid & 31, ty = tid >> 5;
    float acc[4] = {0.f, 0.f, 0.f, 0.f};
    for (int kc = 0; kc < CG; kc += 32) {
        int r = tid >> 3, kq = (tid & 7) * 4;
        float4 a4 = *reinterpret_cast<const float4*>(&guide[(size_t)(row0 + r) * CG + kc + kq]);
        As[r][kq] = a4.x; As[r][kq + 1] = a4.y; As[r][kq + 2] = a4.z; As[r][kq + 3] = a4.w;
        float4 b4 = *reinterpret_cast<const float4*>(&Wg[(size_t)(col0 + r) * CG + kc + kq]);
        Bs[r][kq] = b4.x; Bs[r][kq + 1] = b4.y; Bs[r][kq + 2] = b4.z; Bs[r][kq + 3] = b4.w;
        __syncthreads();
        #pragma unroll
        for (int k = 0; k < 32; k++) {
            float bv = Bs[tx][k];
            #pragma unroll
            for (int rr = 0; rr < 4; rr++)
                acc[rr] += As[ty + 8 * rr][k] * bv;
        }
        __syncthreads();
    }
    float bias = bg[col0 + tx];
    #pragma unroll
    for (int rr = 0; rr < 4; rr++)
        g_buf[(size_t)(row0 + ty + 8 * rr) * EE + col0 + tx] = acc[rr] + bias;
}

// ---------------- preps -----------------------------------------------------
__global__ void wprep(const float* __restrict__ Wp) {
    int co = blockIdx.x;
    for (int ci = threadIdx.x; ci < CIN; ci += 256) {
        const float* src = Wp + ((size_t)co * CIN + ci) * 9;
        #pragma unroll
        for (int k = 0; k < 9; k++)
            wk_h[((size_t)k * COUT + co) * CIN + ci] = __float2half(src[k]);
    }
}

__global__ void weprep(const float* __restrict__ We) {
    int e = blockIdx.x;
    for (int ci = threadIdx.x; ci < CIN; ci += 256)
        we_h[(size_t)e * CIN + ci] = __float2half(We[(size_t)e * CIN + ci]);
}

// x(r,c) -> padded fp16 at pi = r*41 + c; also writes pad zeros (no zinit)
__global__ void xprep(const float* __restrict__ x) {
    __shared__ float s[64][41];
    int r  = blockIdx.x;
    int cc = blockIdx.y * 64;
    int b  = blockIdx.z;
    for (int idx = threadIdx.x; idx < 64 * 40; idx += 256) {
        int ci = idx / 40, c = idx % 40;
        s[ci][c] = x[((size_t)(b * CIN + cc + ci)) * HW + r * WW + c];
    }
    __syncthreads();
    // interior + this row's shared pad column (c = 40)
    for (int idx = threadIdx.x; idx < 41 * 64; idx += 256) {
        int c = idx >> 6, ci = idx & 63;
        float v = (c < 40) ? s[ci][c] : 0.f;
        size_t off = ((size_t)b * PBUF + XOFF + r * 41 + c) * CIN + cc + ci;
        xp_hi[off] = __float2half(v);
    }
    // guard slots: [0, XOFF) and [XOFF+1640, PBUF)
    if (r == 0) {
        for (int idx = threadIdx.x; idx < (XOFF + (PBUF - XOFF - 1640)) * 64; idx += 256) {
            int sl = idx >> 6, ci = idx & 63;
            int slot = (sl < XOFF) ? sl : (XOFF + 1640 + sl - XOFF);
            xp_hi[((size_t)b * PBUF + slot) * CIN + cc + ci] = __half(0.f);
        }
    }
}

// =============== conv machinery: 256(M) x 128(N), 16 warps, 64x32 tile ======
#define S_BHI  32768
#define STG    49152       // A 32K | B 16K
#define CSMEM  147456      // 3 stages
#define CNSTEP 72

struct FragC { float acc[4][4][4]; };

__device__ __forceinline__ void ld_step512(uint32_t st, const char* a_src,
                                           const char* bh, int tid) {
    #pragma unroll
    for (int i = 0; i < 4; i++) {        // A: 2048 cp16 (256 rows x 128B)
        int id = tid + i * 512;
        int row = id >> 3, ch = id & 7;
        cp16(st + SW128(row * 128 + ch * 16), a_src + (size_t)row * 1024 + ch * 16);
    }
    #pragma unroll
    for (int i = 0; i < 2; i++) {        // B: 1024 cp16 (128 rows x 128B)
        int id = tid + i * 512;
        int row = id >> 3, ch = id & 7;
        cp16(st + S_BHI + SW128(row * 128 + ch * 16), bh + (size_t)row * 1024 + ch * 16);
    }
    asm volatile("cp.async.commit_group;" ::: "memory");
}

__device__ __forceinline__ void mma_stepC(uint32_t st, int wm, int wn, int lane,
                                          FragC& f) {
    int lr    = lane & 15;
    int ahalf = ((lane >> 4) & 1) * 16;
    int brow  = ((lane >> 4) & 1) * 8 + (lane & 7);
    int bhalf = ((lane >> 3) & 1) * 16;
    #pragma unroll
    for (int kk = 0; kk < 4; kk++) {
        uint32_t bh[2][4];
        #pragma unroll
        for (int bt = 0; bt < 2; bt++) {
            uint32_t off = SW128((uint32_t)(wn * 32 + bt * 16 + brow) * 128 + kk * 32 + bhalf);
            LDSM_X4(bh[bt], st + S_BHI + off);
        }
        #pragma unroll
        for (int mt = 0; mt < 4; mt++) {
            uint32_t a[4];
            uint32_t off = SW128((uint32_t)(wm * 64 + mt * 16 + lr) * 128 + kk * 32 + ahalf);
            LDSM_X4(a, st + off);
            #pragma unroll
            for (int nt = 0; nt < 4; nt++) {
                int bt = nt >> 1, pp = (nt & 1) * 2;
                MMA16816(f.acc[mt][nt], a, bh[bt][pp], bh[bt][pp + 1]);
            }
        }
    }
}

__device__ __forceinline__ void conv_load(uint32_t sb, int s, int cobase,
                                          int q0, int b, int tid) {
    int k = s >> 3, cc = s & 7;
    int kh = k / 3, kw = k - kh * 3;
    uint32_t st = sb + (uint32_t)(s % 3) * STG;
    const char* a_src = (const char*)(wk_h + ((size_t)k * COUT + cobase) * CIN + cc * 64);
    size_t xoff = ((size_t)b * PBUF + XOFF + q0 + (kh - 1) * 41 + (kw - 1)) * CIN + cc * 64;
    ld_step512(st, a_src, (const char*)(xp_hi + xoff), tid);
}

__global__ void __launch_bounds__(512, 1)
conv_mma(const float* __restrict__ gamma_p,
         const float* __restrict__ beta_p,
         float* __restrict__ out) {
    extern __shared__ __align__(1024) char smem[];
    uint32_t sb = smem_u32(smem);
    int tid = threadIdx.x, wid = tid >> 5, lane = tid & 31;
    int q0     = blockIdx.x * 128;
    int cobase = blockIdx.y * 256;
    int b      = blockIdx.z;
    int wm = wid >> 2, wn = wid & 3;

    FragC f;
    #pragma unroll
    for (int mt = 0; mt < 4; mt++)
        #pragma unroll
        for (int nt = 0; nt < 4; nt++)
            #pragma unroll
            for (int r = 0; r < 4; r++) f.acc[mt][nt][r] = 0.f;

    conv_load(sb, 0, cobase, q0, b, tid);
    conv_load(sb, 1, cobase, q0, b, tid);
    for (int s = 0; s < CNSTEP; s++) {
        if (s + 1 < CNSTEP) asm volatile("cp.async.wait_group 1;" ::: "memory");
        else                asm volatile("cp.async.wait_group 0;" ::: "memory");
        __syncthreads();
        if (s + 2 < CNSTEP) conv_load(sb, s + 2, cobase, q0, b, tid);
        mma_stepC(sb + (uint32_t)(s % 3) * STG, wm, wn, lane, f);
    }

    // epilogue: BN + sigmoid gate; pi -> (r,c); guarded stores
    int head = (cobase >> 6) + wm;
    int qb = q0 + wn * 32;
    float inv = rsqrtf(1.0f + BN_EPS);
    float av[4][2];
    int hwv[4][2];
    #pragma unroll
    for (int nt = 0; nt < 4; nt++) {
        #pragma unroll
        for (int e = 0; e < 2; e++) {
            int qq = qb + nt * 8 + (lane & 3) * 2 + e;
            int pr = qq / 41, pc = qq - pr * 41;
            bool ok = (pc < 40 && pr < 40);
            int hw = pr * 40 + pc;
            hwv[nt][e] = ok ? hw : -1;
            av[nt][e] = ok ? attn_buf[(size_t)(b * NH + head) * HW + hw] : 0.f;
        }
    }
    #pragma unroll
    for (int mt = 0; mt < 4; mt++) {
        int r0 = cobase + wm * 64 + mt * 16 + (lane >> 2);
        float sc0 = gamma_p[r0] * inv,     bt0 = beta_p[r0];
        float sc8 = gamma_p[r0 + 8] * inv, bt8 = beta_p[r0 + 8];
        #pragma unroll
        for (int nt = 0; nt < 4; nt++) {
            #pragma unroll
            for (int e = 0; e < 2; e++) {
                int hw = hwv[nt][e];
                if (hw >= 0) {
                    out[((size_t)(b * COUT + r0)) * HW + hw]     = (f.acc[mt][nt][e]     * sc0 + bt0) * av[nt][e];
                    out[((size_t)(b * COUT + r0 + 8)) * HW + hw] = (f.acc[mt][nt][e + 2] * sc8 + bt8) * av[nt][e];
                }
            }
        }
    }
}

// =============== embed 1x1 (M=256=all E) + fused attn: 256 thr, 64x64 tile ==
#define ENSTEP 8
#define TS 260                           // tile row stride in floats
#define G_OFF (128 * TS)                 // g region offset (floats)
#define ESMEM 215040                     // 128*260*4 + 80*256*4

struct FragE { float acc[4][8][4]; };

__device__ __forceinline__ void ld_step256(uint32_t st, const char* a_src,
                                           const char* bh, int tid) {
    #pragma unroll
    for (int i = 0; i < 8; i++) {
        int id = tid + i * 256;
        int row = id >> 3, ch = id & 7;
        cp16(st + SW128(row * 128 + ch * 16), a_src + (size_t)row * 1024 + ch * 16);
    }
    #pragma unroll
    for (int i = 0; i < 4; i++) {
        int id = tid + i * 256;
        int row = id >> 3, ch = id & 7;
        cp16(st + S_BHI + SW128(row * 128 + ch * 16), bh + (size_t)row * 1024 + ch * 16);
    }
    asm volatile("cp.async.commit_group;" ::: "memory");
}

__device__ __forceinline__ void mma_stepE(uint32_t st, int wm, int wn, int lane,
                                          FragE& f) {
    int lr    = lane & 15;
    int ahalf = ((lane >> 4) & 1) * 16;
    int brow  = ((lane >> 4) & 1) * 8 + (lane & 7);
    int bhalf = ((lane >> 3) & 1) * 16;
    #pragma unroll
    for (int kk = 0; kk < 4; kk++) {
        uint32_t bh[4][4];
        #pragma unroll
        for (int bt = 0; bt < 4; bt++) {
            uint32_t off = SW128((uint32_t)(wn * 64 + bt * 16 + brow) * 128 + kk * 32 + bhalf);
            LDSM_X4(bh[bt], st + S_BHI + off);
        }
        #pragma unroll
        for (int mt = 0; mt < 4; mt++) {
            uint32_t a[4];
            uint32_t off = SW128((uint32_t)(wm * 64 + mt * 16 + lr) * 128 + kk * 32 + ahalf);
            LDSM_X4(a, st + off);
            #pragma unroll
            for (int nt = 0; nt < 8; nt++) {
                int bt = nt >> 1, pp = (nt & 1) * 2;
                MMA16816(f.acc[mt][nt], a, bh[bt][pp], bh[bt][pp + 1]);
            }
        }
    }
}

__device__ __forceinline__ void embed_load(uint32_t sb, int s, int q0, int b, int tid) {
    uint32_t st = sb + (uint32_t)(s & 1) * STG;
    const char* a_src = (const char*)(we_h + s * 64);
    size_t xoff = ((size_t)b * PBUF + XOFF + q0) * CIN + s * 64;
    ld_step256(st, a_src, (const char*)(xp_hi + xoff), tid);
}

__global__ void __launch_bounds__(256, 1)
embed_attn(const float* __restrict__ gamma_e,
           const float* __restrict__ beta_e,
           const float* __restrict__ head_bias) {
    extern __shared__ __align__(1024) char smem[];
    uint32_t sb = smem_u32(smem);
    int tid = threadIdx.x, wid = tid >> 5, lane = tid & 31;
    int q0 = blockIdx.x * 128;
    int b  = blockIdx.z;
    int wm = wid >> 1, wn = wid & 1;

    FragE f;
    #pragma unroll
    for (int mt = 0; mt < 4; mt++)
        #pragma unroll
        for (int nt = 0; nt < 8; nt++)
            #pragma unroll
            for (int r = 0; r < 4; r++) f.acc[mt][nt][r] = 0.f;

    embed_load(sb, 0, q0, b, tid);
    for (int s = 0; s < ENSTEP; s++) {
        asm volatile("cp.async.wait_group 0;" ::: "memory");
        __syncthreads();
        if (s + 1 < ENSTEP) embed_load(sb, s + 1, q0, b, tid);
        mma_stepE(sb + (uint32_t)(s & 1) * STG, wm, wn, lane, f);
    }
    __syncthreads();   // stage buffers reused as tile below

    // BN + transpose into tile[q][e]
    float* tile = reinterpret_cast<float*>(smem);
    float inv = rsqrtf(1.0f + BN_EPS);
    #pragma unroll
    for (int mt = 0; mt < 4; mt++) {
        int er = wm * 64 + mt * 16 + (lane >> 2);
        float sc0 = gamma_e[er] * inv,     bt0 = beta_e[er];
        float sc8 = gamma_e[er + 8] * inv, bt8 = beta_e[er + 8];
        #pragma unroll
        for (int nt = 0; nt < 8; nt++) {
            int ql = wn * 64 + nt * 8 + (lane & 3) * 2;
            tile[ql * TS + er]           = f.acc[mt][nt][0] * sc0 + bt0;
            tile[(ql + 1) * TS + er]     = f.acc[mt][nt][1] * sc0 + bt0;
            tile[ql * TS + er + 8]       = f.acc[mt][nt][2] * sc8 + bt8;
            tile[(ql + 1) * TS + er + 8] = f.acc[mt][nt][3] * sc8 + bt8;
        }
    }
    // stage g[b]: 80 x 256 floats
    float* gsm = tile + G_OFF;
    const float* gsrc = g_buf + (size_t)b * NTOK * EE;
    for (int i = tid; i < NTOK * EE / 4; i += 256)
        reinterpret_cast<float4*>(gsm)[i] = reinterpret_cast<const float4*>(gsrc)[i];
    __syncthreads();

    // attn: per thread, q = tid&127, 4 heads
    int q = tid & 127;
    int qq = q0 + q;
    int pr = qq / 41, pc = qq - pr * 41;
    bool valid = (pc < 40 && pr < 40);
    int hw = pr * 40 + pc;
    #pragma unroll
    for (int p = 0; p < 4; p++) {
        int m = (tid >> 7) + p * 2;
        float4 ev[8];
        #pragma unroll
        for (int j = 0; j < 8; j++)
            ev[j] = *reinterpret_cast<const float4*>(&tile[q * TS + m * HC + j * 4]);
        float maxv = -3.4e38f;
        for (int n = 0; n < NTOK; n++) {
            const float4* gp = reinterpret_cast<const float4*>(&gsm[n * EE + m * HC]);
            float acc = 0.f;
            #pragma unroll
            for (int j = 0; j < 8; j++) {
                float4 g4 = gp[j];
                acc += ev[j].x * g4.x + ev[j].y * g4.y + ev[j].z * g4.z + ev[j].w * g4.w;
            }
            maxv = fmaxf(maxv, acc);
        }
        float a = maxv * 0.17677669529663687f + head_bias[m];
        float s = 1.0f / (1.0f + expf(-a));
        if (valid) attn_buf[(size_t)(b * NH + m) * HW + hw] = s;
    }
}

extern "C" void kernel_launch(void* const* d_in, const int* in_sizes, int n_in,
                              void* d_out, int out_size) {
    const float* x         = (const float*)d_in[0];
    const float* guide     = (const float*)d_in[1];
    const float* We        = (const float*)d_in[2];
    const float* gamma_e   = (const float*)d_in[3];
    const float* beta_e    = (const float*)d_in[4];
    const float* Wg        = (const float*)d_in[5];
    const float* bg        = (const float*)d_in[6];
    const float* head_bias = (const float*)d_in[7];
    const float* Wp        = (const float*)d_in[8];
    const float* gamma_p   = (const float*)d_in[9];
    const float* beta_p    = (const float*)d_in[10];
    float* out = (float*)d_out;

    guide_gemm<<<dim3(40, 8), 256>>>(guide, Wg, bg);
    wprep<<<512, 256>>>(Wp);
    weprep<<<256, 256>>>(We);
    xprep<<<dim3(40, 8, 16), 256>>>(x);
    cudaFuncSetAttribute(embed_attn, cudaFuncAttributeMaxDynamicSharedMemorySize, ESMEM);
    embed_attn<<<dim3(13, 1, 16), 256, ESMEM>>>(gamma_e, beta_e, head_bias);
    cudaFuncSetAttribute(conv_mma, cudaFuncAttributeMaxDynamicSharedMemorySize, CSMEM);
    conv_mma<<<dim3(13, 2, 16), 512, CSMEM>>>(gamma_p, beta_p, out);
}

// round 10
// speedup vs baseline: 1.1118x; 1.1118x over previous
#include <cuda_runtime.h>
#include <cuda_fp16.h>
#include <cstdint>

#define BB   16
#define CIN  512
#define HH   40
#define WW   40
#define HW   1600
#define NTOK 80
#define CG   512
#define EE   256
#define COUT 512
#define NH   8
#define HC   32
#define BN_EPS 1e-3f
// 41-stride shared-pad pixel space: pi = r*41 + c, slot c=40 of each row = shared pad
#define PBUF 1792
#define XOFF 64

// ------------------------------ scratch (device globals) -------------------
__device__ float g_buf[BB * NTOK * EE];
__device__ float attn_buf[BB * NH * HW];
__device__ __align__(256) __half xp_hi[(size_t)BB * PBUF * CIN];
__device__ __align__(256) __half wk_h[(size_t)9 * COUT * CIN];
__device__ __align__(256) __half we_h[EE * CIN];

// ------------------------------ helpers ------------------------------------
__device__ __forceinline__ uint32_t smem_u32(const void* p) {
    uint32_t a;
    asm("{ .reg .u64 t; cvta.to.shared.u64 t, %1; cvt.u32.u64 %0, t; }" : "=r"(a) : "l"(p));
    return a;
}
#define SW128(off) ((off) ^ (((off) >> 3) & 0x70))

__device__ __forceinline__ void cp16(uint32_t dst, const void* src) {
    asm volatile("cp.async.cg.shared.global [%0], [%1], 16;" :: "r"(dst), "l"(src));
}

#define LDSM_X4(r, a) \
    asm volatile("ldmatrix.sync.aligned.m8n8.x4.shared.b16 {%0,%1,%2,%3}, [%4];" \
        : "=r"((r)[0]), "=r"((r)[1]), "=r"((r)[2]), "=r"((r)[3]) : "r"(a))

#define MMA16816(d, a, b0, b1) \
    asm volatile("mma.sync.aligned.m16n8k16.row.col.f32.f16.f16.f32 " \
        "{%0,%1,%2,%3}, {%4,%5,%6,%7}, {%8,%9}, {%0,%1,%2,%3};" \
        : "+f"((d)[0]), "+f"((d)[1]), "+f"((d)[2]), "+f"((d)[3]) \
        : "r"((a)[0]), "r"((a)[1]), "r"((a)[2]), "r"((a)[3]), "r"(b0), "r"(b1))

// ---------------- guide FC  g = guide @ Wg^T + bg ---------------------------
__global__ void guide_gemm(const float* __restrict__ guide,
                           const float* __restrict__ Wg,
                           const float* __restrict__ bg) {
    __shared__ float As[32][33];
    __shared__ float Bs[32][33];
    int tid  = threadIdx.x;
    int row0 = blockIdx.x * 32;
    int col0 = blockIdx.y * 32;
    int tx = tid & 31, ty = tid >> 5;
    float acc[4] = {0.f, 0.f, 0.f, 0.f};
    for (int kc = 0; kc < CG; kc += 32) {
        int r = tid >> 3, kq = (tid & 7) * 4;
        float4 a4 = *reinterpret_cast<const float4*>(&guide[(size_t)(row0 + r) * CG + kc + kq]);
        As[r][kq] = a4.x; As[r][kq + 1] = a4.y; As[r][kq + 2] = a4.z; As[r][kq + 3] = a4.w;
        float4 b4 = *reinterpret_cast<const float4*>(&Wg[(size_t)(col0 + r) * CG + kc + kq]);
        Bs[r][kq] = b4.x; Bs[r][kq + 1] = b4.y; Bs[r][kq + 2] = b4.z; Bs[r][kq + 3] = b4.w;
        __syncthreads();
        #pragma unroll
        for (int k = 0; k < 32; k++) {
            float bv = Bs[tx][k];
            #pragma unroll
            for (int rr = 0; rr < 4; rr++)
                acc[rr] += As[ty + 8 * rr][k] * bv;
        }
        __syncthreads();
    }
    float bias = bg[col0 + tx];
    #pragma unroll
    for (int rr = 0; rr < 4; rr++)
        g_buf[(size_t)(row0 + ty + 8 * rr) * EE + col0 + tx] = acc[rr] + bias;
}

// ---------------- merged weight prep (Wp -> wk_h, We -> we_h) ---------------
__global__ void wprep(const float* __restrict__ Wp, const float* __restrict__ We) {
    int co = blockIdx.x;
    if (co < COUT) {
        for (int ci = threadIdx.x; ci < CIN; ci += 256) {
            const float* src = Wp + ((size_t)co * CIN + ci) * 9;
            #pragma unroll
            for (int k = 0; k < 9; k++)
                wk_h[((size_t)k * COUT + co) * CIN + ci] = __float2half(src[k]);
        }
    } else {
        int e = co - COUT;
        for (int ci = threadIdx.x; ci < CIN; ci += 256)
            we_h[(size_t)e * CIN + ci] = __float2half(We[(size_t)e * CIN + ci]);
    }
}

// x(r,c) -> padded fp16 at pi = r*41 + c; vectorized 16B stores; pads included
__global__ void xprep(const float* __restrict__ x) {
    __shared__ float s[64][41];
    int r  = blockIdx.x;
    int cc = blockIdx.y * 64;
    int b  = blockIdx.z;
    for (int idx = threadIdx.x; idx < 64 * 40; idx += 256) {
        int ci = idx / 40, c = idx % 40;
        s[ci][c] = x[((size_t)(b * CIN + cc + ci)) * HW + r * WW + c];
    }
    __syncthreads();
    // interior + shared pad column (c = 40): 41 cols x 8 ci-groups
    for (int idx = threadIdx.x; idx < 41 * 8; idx += 256) {
        int c = idx >> 3, cg = idx & 7;
        __half h8[8];
        #pragma unroll
        for (int j = 0; j < 8; j++)
            h8[j] = __float2half((c < 40) ? s[cg * 8 + j][c] : 0.f);
        size_t off = ((size_t)b * PBUF + XOFF + r * 41 + c) * CIN + cc + cg * 8;
        *reinterpret_cast<uint4*>(&xp_hi[off]) = *reinterpret_cast<const uint4*>(h8);
    }
    // guard slots: [0, XOFF) and [XOFF+1640, PBUF): 152 slots
    if (r == 0) {
        uint4 z = {0, 0, 0, 0};
        for (int idx = threadIdx.x; idx < 152 * 8; idx += 256) {
            int sl = idx >> 3, cg = idx & 7;
            int slot = (sl < XOFF) ? sl : (XOFF + 1640 + sl - XOFF);
            *reinterpret_cast<uint4*>(&xp_hi[((size_t)b * PBUF + slot) * CIN + cc + cg * 8]) = z;
        }
    }
}

// =============== conv: CTA 128(M) x 128(N), 8 warps 64x32, 2 CTAs/SM ========
#define C_BHI  16384
#define CSTG   32768       // A 16K | B 16K
#define CSMEM  98304       // 3 stages
#define CNSTEP 72

struct FragC { float acc[4][4][4]; };

__device__ __forceinline__ void conv_load(uint32_t sb, int s, int cobase,
                                          int q0, int b, int tid) {
    int k = s >> 3, cc = s & 7;
    int kh = k / 3, kw = k - kh * 3;
    uint32_t st = sb + (uint32_t)(s % 3) * CSTG;
    const char* a_src = (const char*)(wk_h + ((size_t)k * COUT + cobase) * CIN + cc * 64);
    size_t xoff = ((size_t)b * PBUF + XOFF + q0 + (kh - 1) * 41 + (kw - 1)) * CIN + cc * 64;
    const char* b_src = (const char*)(xp_hi + xoff);
    #pragma unroll
    for (int i = 0; i < 4; i++) {        // A: 1024 cp16 (128 rows x 128B)
        int id = tid + i * 256;
        int row = id >> 3, ch = id & 7;
        cp16(st + SW128(row * 128 + ch * 16), a_src + (size_t)row * 1024 + ch * 16);
    }
    #pragma unroll
    for (int i = 0; i < 4; i++) {        // B: 1024 cp16 (128 rows x 128B)
        int id = tid + i * 256;
        int row = id >> 3, ch = id & 7;
        cp16(st + C_BHI + SW128(row * 128 + ch * 16), b_src + (size_t)row * 1024 + ch * 16);
    }
    asm volatile("cp.async.commit_group;" ::: "memory");
}

__device__ __forceinline__ void mma_stepC(uint32_t st, int wm, int wn, int lane,
                                          FragC& f) {
    int lr    = lane & 15;
    int ahalf = ((lane >> 4) & 1) * 16;
    int brow  = ((lane >> 4) & 1) * 8 + (lane & 7);
    int bhalf = ((lane >> 3) & 1) * 16;
    #pragma unroll
    for (int kk = 0; kk < 4; kk++) {
        uint32_t bh[2][4];
        #pragma unroll
        for (int bt = 0; bt < 2; bt++) {
            uint32_t off = SW128((uint32_t)(wn * 32 + bt * 16 + brow) * 128 + kk * 32 + bhalf);
            LDSM_X4(bh[bt], st + C_BHI + off);
        }
        #pragma unroll
        for (int mt = 0; mt < 4; mt++) {
            uint32_t a[4];
            uint32_t off = SW128((uint32_t)(wm * 64 + mt * 16 + lr) * 128 + kk * 32 + ahalf);
            LDSM_X4(a, st + off);
            #pragma unroll
            for (int nt = 0; nt < 4; nt++) {
                int bt = nt >> 1, pp = (nt & 1) * 2;
                MMA16816(f.acc[mt][nt], a, bh[bt][pp], bh[bt][pp + 1]);
            }
        }
    }
}

__global__ void __launch_bounds__(256, 2)
conv_mma(const float* __restrict__ gamma_p,
         const float* __restrict__ beta_p,
         float* __restrict__ out) {
    extern __shared__ __align__(1024) char smem[];
    uint32_t sb = smem_u32(smem);
    int tid = threadIdx.x, wid = tid >> 5, lane = tid & 31;
    int q0     = blockIdx.x * 128;
    int cobase = blockIdx.y * 128;
    int b      = blockIdx.z;
    int wm = wid >> 2, wn = wid & 3;

    FragC f;
    #pragma unroll
    for (int mt = 0; mt < 4; mt++)
        #pragma unroll
        for (int nt = 0; nt < 4; nt++)
            #pragma unroll
            for (int r = 0; r < 4; r++) f.acc[mt][nt][r] = 0.f;

    conv_load(sb, 0, cobase, q0, b, tid);
    conv_load(sb, 1, cobase, q0, b, tid);
    for (int s = 0; s < CNSTEP; s++) {
        if (s + 1 < CNSTEP) asm volatile("cp.async.wait_group 1;" ::: "memory");
        else                asm volatile("cp.async.wait_group 0;" ::: "memory");
        __syncthreads();
        if (s + 2 < CNSTEP) conv_load(sb, s + 2, cobase, q0, b, tid);
        mma_stepC(sb + (uint32_t)(s % 3) * CSTG, wm, wn, lane, f);
    }

    // epilogue: BN + sigmoid gate; pi -> (r,c); guarded stores
    int head = (cobase >> 6) + wm;
    int qb = q0 + wn * 32;
    float inv = rsqrtf(1.0f + BN_EPS);
    float av[4][2];
    int hwv[4][2];
    #pragma unroll
    for (int nt = 0; nt < 4; nt++) {
        #pragma unroll
        for (int e = 0; e < 2; e++) {
            int qq = qb + nt * 8 + (lane & 3) * 2 + e;
            int pr = qq / 41, pc = qq - pr * 41;
            bool ok = (pc < 40 && pr < 40);
            int hw = pr * 40 + pc;
            hwv[nt][e] = ok ? hw : -1;
            av[nt][e] = ok ? attn_buf[(size_t)(b * NH + head) * HW + hw] : 0.f;
        }
    }
    #pragma unroll
    for (int mt = 0; mt < 4; mt++) {
        int r0 = cobase + wm * 64 + mt * 16 + (lane >> 2);
        float sc0 = gamma_p[r0] * inv,     bt0 = beta_p[r0];
        float sc8 = gamma_p[r0 + 8] * inv, bt8 = beta_p[r0 + 8];
        #pragma unroll
        for (int nt = 0; nt < 4; nt++) {
            #pragma unroll
            for (int e = 0; e < 2; e++) {
                int hw = hwv[nt][e];
                if (hw >= 0) {
                    out[((size_t)(b * COUT + r0)) * HW + hw]     = (f.acc[mt][nt][e]     * sc0 + bt0) * av[nt][e];
                    out[((size_t)(b * COUT + r0 + 8)) * HW + hw] = (f.acc[mt][nt][e + 2] * sc8 + bt8) * av[nt][e];
                }
            }
        }
    }
}

// =============== embed 1x1 (M=256=all E) + fused attn: 512 thr, 64x32 tile ==
#define E_BHI  32768
#define ESTG   49152       // A 32K | B 16K
#define ENSTEP 8
#define TS 260                           // tile row stride in floats
#define G_OFF (128 * TS)                 // g region offset (floats)
#define ESMEM 215040                     // 128*260*4 + 80*256*4

__device__ __forceinline__ void embed_load(uint32_t sb, int s, int q0, int b, int tid) {
    uint32_t st = sb + (uint32_t)(s & 1) * ESTG;
    const char* a_src = (const char*)(we_h + s * 64);
    size_t xoff = ((size_t)b * PBUF + XOFF + q0) * CIN + s * 64;
    const char* b_src = (const char*)(xp_hi + xoff);
    #pragma unroll
    for (int i = 0; i < 4; i++) {        // A: 2048 cp16 (256 rows x 128B)
        int id = tid + i * 512;
        int row = id >> 3, ch = id & 7;
        cp16(st + SW128(row * 128 + ch * 16), a_src + (size_t)row * 1024 + ch * 16);
    }
    #pragma unroll
    for (int i = 0; i < 2; i++) {        // B: 1024 cp16 (128 rows x 128B)
        int id = tid + i * 512;
        int row = id >> 3, ch = id & 7;
        cp16(st + E_BHI + SW128(row * 128 + ch * 16), b_src + (size_t)row * 1024 + ch * 16);
    }
    asm volatile("cp.async.commit_group;" ::: "memory");
}

__device__ __forceinline__ void mma_stepE(uint32_t st, int wm, int wn, int lane,
                                          FragC& f) {
    int lr    = lane & 15;
    int ahalf = ((lane >> 4) & 1) * 16;
    int brow  = ((lane >> 4) & 1) * 8 + (lane & 7);
    int bhalf = ((lane >> 3) & 1) * 16;
    #pragma unroll
    for (int kk = 0; kk < 4; kk++) {
        uint32_t bh[2][4];
        #pragma unroll
        for (int bt = 0; bt < 2; bt++) {
            uint32_t off = SW128((uint32_t)(wn * 32 + bt * 16 + brow) * 128 + kk * 32 + bhalf);
            LDSM_X4(bh[bt], st + E_BHI + off);
        }
        #pragma unroll
        for (int mt = 0; mt < 4; mt++) {
            uint32_t a[4];
            uint32_t off = SW128((uint32_t)(wm * 64 + mt * 16 + lr) * 128 + kk * 32 + ahalf);
            LDSM_X4(a, st + off);
            #pragma unroll
            for (int nt = 0; nt < 4; nt++) {
                int bt = nt >> 1, pp = (nt & 1) * 2;
                MMA16816(f.acc[mt][nt], a, bh[bt][pp], bh[bt][pp + 1]);
            }
        }
    }
}

__global__ void __launch_bounds__(512, 1)
embed_attn(const float* __restrict__ gamma_e,
           const float* __restrict__ beta_e,
           const float* __restrict__ head_bias) {
    extern __shared__ __align__(1024) char smem[];
    uint32_t sb = smem_u32(smem);
    int tid = threadIdx.x, wid = tid >> 5, lane = tid & 31;
    int q0 = blockIdx.x * 128;
    int b  = blockIdx.z;
    int wm = wid >> 2, wn = wid & 3;

    FragC f;
    #pragma unroll
    for (int mt = 0; mt < 4; mt++)
        #pragma unroll
        for (int nt = 0; nt < 4; nt++)
            #pragma unroll
            for (int r = 0; r < 4; r++) f.acc[mt][nt][r] = 0.f;

    embed_load(sb, 0, q0, b, tid);
    for (int s = 0; s < ENSTEP; s++) {
        asm volatile("cp.async.wait_group 0;" ::: "memory");
        __syncthreads();
        if (s + 1 < ENSTEP) embed_load(sb, s + 1, q0, b, tid);
        mma_stepE(sb + (uint32_t)(s & 1) * ESTG, wm, wn, lane, f);
    }
    __syncthreads();   // stage buffers reused as tile below

    // BN + transpose into tile[q][e]
    float* tile = reinterpret_cast<float*>(smem);
    float inv = rsqrtf(1.0f + BN_EPS);
    #pragma unroll
    for (int mt = 0; mt < 4; mt++) {
        int er = wm * 64 + mt * 16 + (lane >> 2);
        float sc0 = gamma_e[er] * inv,     bt0 = beta_e[er];
        float sc8 = gamma_e[er + 8] * inv, bt8 = beta_e[er + 8];
        #pragma unroll
        for (int nt = 0; nt < 4; nt++) {
            int ql = wn * 32 + nt * 8 + (lane & 3) * 2;
            tile[ql * TS + er]           = f.acc[mt][nt][0] * sc0 + bt0;
            tile[(ql + 1) * TS + er]     = f.acc[mt][nt][1] * sc0 + bt0;
            tile[ql * TS + er + 8]       = f.acc[mt][nt][2] * sc8 + bt8;
            tile[(ql + 1) * TS + er + 8] = f.acc[mt][nt][3] * sc8 + bt8;
        }
    }
    // stage g[b]: 80 x 256 floats
    float* gsm = tile + G_OFF;
    const float* gsrc = g_buf + (size_t)b * NTOK * EE;
    for (int i = tid; i < NTOK * EE / 4; i += 512)
        reinterpret_cast<float4*>(gsm)[i] = reinterpret_cast<const float4*>(gsrc)[i];
    __syncthreads();

    // attn: per thread, q = tid&127, 2 heads
    int q = tid & 127;
    int qq = q0 + q;
    int pr = qq / 41, pc = qq - pr * 41;
    bool valid = (pc < 40 && pr < 40);
    int hw = pr * 40 + pc;
    #pragma unroll
    for (int p = 0; p < 2; p++) {
        int m = (tid >> 7) + p * 4;
        float4 ev[8];
        #pragma unroll
        for (int j = 0; j < 8; j++)
            ev[j] = *reinterpret_cast<const float4*>(&tile[q * TS + m * HC + j * 4]);
        float maxv = -3.4e38f;
        for (int n = 0; n < NTOK; n++) {
            const float4* gp = reinterpret_cast<const float4*>(&gsm[n * EE + m * HC]);
            float acc = 0.f;
            #pragma unroll
            for (int j = 0; j < 8; j++) {
                float4 g4 = gp[j];
                acc += ev[j].x * g4.x + ev[j].y * g4.y + ev[j].z * g4.z + ev[j].w * g4.w;
            }
            maxv = fmaxf(maxv, acc);
        }
        float a = maxv * 0.17677669529663687f + head_bias[m];
        float s = 1.0f / (1.0f + expf(-a));
        if (valid) attn_buf[(size_t)(b * NH + m) * HW + hw] = s;
    }
}

extern "C" void kernel_launch(void* const* d_in, const int* in_sizes, int n_in,
                              void* d_out, int out_size) {
    const float* x         = (const float*)d_in[0];
    const float* guide     = (const float*)d_in[1];
    const float* We        = (const float*)d_in[2];
    const float* gamma_e   = (const float*)d_in[3];
    const float* beta_e    = (const float*)d_in[4];
    const float* Wg        = (const float*)d_in[5];
    const float* bg        = (const float*)d_in[6];
    const float* head_bias = (const float*)d_in[7];
    const float* Wp        = (const float*)d_in[8];
    const float* gamma_p   = (const float*)d_in[9];
    const float* beta_p    = (const float*)d_in[10];
    float* out = (float*)d_out;

    xprep<<<dim3(40, 8, 16), 256>>>(x);
    wprep<<<768, 256>>>(Wp, We);
    guide_gemm<<<dim3(40, 8), 256>>>(guide, Wg, bg);
    cudaFuncSetAttribute(embed_attn, cudaFuncAttributeMaxDynamicSharedMemorySize, ESMEM);
    embed_attn<<<dim3(13, 1, 16), 512, ESMEM>>>(gamma_e, beta_e, head_bias);
    cudaFuncSetAttribute(conv_mma, cudaFuncAttributeMaxDynamicSharedMemorySize, CSMEM);
    conv_mma<<<dim3(13, 4, 16), 256, CSMEM>>>(gamma_p, beta_p, out);
}

// round 11
// speedup vs baseline: 1.2284x; 1.1049x over previous
#include <cuda_runtime.h>
#include <cuda_fp16.h>
#include <cstdint>

#define BB   16
#define CIN  512
#define HH   40
#define WW   40
#define HW   1600
#define NTOK 80
#define CG   512
#define EE   256
#define COUT 512
#define NH   8
#define HC   32
#define BN_EPS 1e-3f
// 41-stride shared-pad pixel space: pi = r*41 + c, slot c=40 of each row = shared pad
#define PBUF 1792
#define XOFF 64

// ------------------------------ scratch (device globals) -------------------
__device__ float g_buf[BB * NTOK * EE];
__device__ float attn_buf[BB * NH * HW];
__device__ __align__(256) __half xp_hi[(size_t)BB * PBUF * CIN];
__device__ __align__(256) __half wk_h[(size_t)9 * COUT * CIN];
__device__ __align__(256) __half we_h[EE * CIN];

// ------------------------------ helpers ------------------------------------
__device__ __forceinline__ uint32_t smem_u32(const void* p) {
    uint32_t a;
    asm("{ .reg .u64 t; cvta.to.shared.u64 t, %1; cvt.u32.u64 %0, t; }" : "=r"(a) : "l"(p));
    return a;
}
#define SW128(off) ((off) ^ (((off) >> 3) & 0x70))

__device__ __forceinline__ void cp16(uint32_t dst, const void* src) {
    asm volatile("cp.async.cg.shared.global [%0], [%1], 16;" :: "r"(dst), "l"(src));
}

#define LDSM_X4(r, a) \
    asm volatile("ldmatrix.sync.aligned.m8n8.x4.shared.b16 {%0,%1,%2,%3}, [%4];" \
        : "=r"((r)[0]), "=r"((r)[1]), "=r"((r)[2]), "=r"((r)[3]) : "r"(a))

#define MMA16816(d, a, b0, b1) \
    asm volatile("mma.sync.aligned.m16n8k16.row.col.f32.f16.f16.f32 " \
        "{%0,%1,%2,%3}, {%4,%5,%6,%7}, {%8,%9}, {%0,%1,%2,%3};" \
        : "+f"((d)[0]), "+f"((d)[1]), "+f"((d)[2]), "+f"((d)[3]) \
        : "r"((a)[0]), "r"((a)[1]), "r"((a)[2]), "r"((a)[3]), "r"(b0), "r"(b1))

// ---------------- guide FC  g = guide @ Wg^T + bg ---------------------------
__global__ void guide_gemm(const float* __restrict__ guide,
                           const float* __restrict__ Wg,
                           const float* __restrict__ bg) {
    __shared__ float As[32][33];
    __shared__ float Bs[32][33];
    int tid  = threadIdx.x;
    int row0 = blockIdx.x * 32;
    int col0 = blockIdx.y * 32;
    int tx = tid & 31, ty = tid >> 5;
    float acc[4] = {0.f, 0.f, 0.f, 0.f};
    for (int kc = 0; kc < CG; kc += 32) {
        int r = tid >> 3, kq = (tid & 7) * 4;
        float4 a4 = *reinterpret_cast<const float4*>(&guide[(size_t)(row0 + r) * CG + kc + kq]);
        As[r][kq] = a4.x; As[r][kq + 1] = a4.y; As[r][kq + 2] = a4.z; As[r][kq + 3] = a4.w;
        float4 b4 = *reinterpret_cast<const float4*>(&Wg[(size_t)(col0 + r) * CG + kc + kq]);
        Bs[r][kq] = b4.x; Bs[r][kq + 1] = b4.y; Bs[r][kq + 2] = b4.z; Bs[r][kq + 3] = b4.w;
        __syncthreads();
        #pragma unroll
        for (int k = 0; k < 32; k++) {
            float bv = Bs[tx][k];
            #pragma unroll
            for (int rr = 0; rr < 4; rr++)
                acc[rr] += As[ty + 8 * rr][k] * bv;
        }
        __syncthreads();
    }
    float bias = bg[col0 + tx];
    #pragma unroll
    for (int rr = 0; rr < 4; rr++)
        g_buf[(size_t)(row0 + ty + 8 * rr) * EE + col0 + tx] = acc[rr] + bias;
}

// ---------------- merged weight prep (Wp -> wk_h, We -> we_h) ---------------
__global__ void wprep(const float* __restrict__ Wp, const float* __restrict__ We) {
    int co = blockIdx.x;
    if (co < COUT) {
        for (int ci = threadIdx.x; ci < CIN; ci += 256) {
            const float* src = Wp + ((size_t)co * CIN + ci) * 9;
            #pragma unroll
            for (int k = 0; k < 9; k++)
                wk_h[((size_t)k * COUT + co) * CIN + ci] = __float2half(src[k]);
        }
    } else {
        int e = co - COUT;
        for (int ci = threadIdx.x; ci < CIN; ci += 256)
            we_h[(size_t)e * CIN + ci] = __float2half(We[(size_t)e * CIN + ci]);
    }
}

// x(r,c) -> padded fp16 at pi = r*41 + c; vectorized 16B stores; pads included
__global__ void xprep(const float* __restrict__ x) {
    __shared__ float s[64][41];
    int r  = blockIdx.x;
    int cc = blockIdx.y * 64;
    int b  = blockIdx.z;
    for (int idx = threadIdx.x; idx < 64 * 40; idx += 256) {
        int ci = idx / 40, c = idx % 40;
        s[ci][c] = x[((size_t)(b * CIN + cc + ci)) * HW + r * WW + c];
    }
    __syncthreads();
    // interior + shared pad column (c = 40): 41 cols x 8 ci-groups
    for (int idx = threadIdx.x; idx < 41 * 8; idx += 256) {
        int c = idx >> 3, cg = idx & 7;
        __half h8[8];
        #pragma unroll
        for (int j = 0; j < 8; j++)
            h8[j] = __float2half((c < 40) ? s[cg * 8 + j][c] : 0.f);
        size_t off = ((size_t)b * PBUF + XOFF + r * 41 + c) * CIN + cc + cg * 8;
        *reinterpret_cast<uint4*>(&xp_hi[off]) = *reinterpret_cast<const uint4*>(h8);
    }
    // guard slots: [0, XOFF) and [XOFF+1640, PBUF): 152 slots
    if (r == 0) {
        uint4 z = {0, 0, 0, 0};
        for (int idx = threadIdx.x; idx < 152 * 8; idx += 256) {
            int sl = idx >> 3, cg = idx & 7;
            int slot = (sl < XOFF) ? sl : (XOFF + 1640 + sl - XOFF);
            *reinterpret_cast<uint4*>(&xp_hi[((size_t)b * PBUF + slot) * CIN + cc + cg * 8]) = z;
        }
    }
}

// =============== conv: CTA 128(M) x 128(N), 8 warps 64x32, 2 CTAs/SM ========
#define C_BHI  16384
#define CSTG   32768       // A 16K | B 16K
#define CSMEM  98304       // 3 stages
#define CNSTEP 72

struct FragC { float acc[4][4][4]; };

__device__ __forceinline__ void conv_load(uint32_t sb, int s, int cobase,
                                          int q0, int b, int tid) {
    int k = s >> 3, cc = s & 7;
    int kh = k / 3, kw = k - kh * 3;
    uint32_t st = sb + (uint32_t)(s % 3) * CSTG;
    const char* a_src = (const char*)(wk_h + ((size_t)k * COUT + cobase) * CIN + cc * 64);
    size_t xoff = ((size_t)b * PBUF + XOFF + q0 + (kh - 1) * 41 + (kw - 1)) * CIN + cc * 64;
    const char* b_src = (const char*)(xp_hi + xoff);
    #pragma unroll
    for (int i = 0; i < 4; i++) {        // A: 1024 cp16 (128 rows x 128B)
        int id = tid + i * 256;
        int row = id >> 3, ch = id & 7;
        cp16(st + SW128(row * 128 + ch * 16), a_src + (size_t)row * 1024 + ch * 16);
    }
    #pragma unroll
    for (int i = 0; i < 4; i++) {        // B: 1024 cp16 (128 rows x 128B)
        int id = tid + i * 256;
        int row = id >> 3, ch = id & 7;
        cp16(st + C_BHI + SW128(row * 128 + ch * 16), b_src + (size_t)row * 1024 + ch * 16);
    }
    asm volatile("cp.async.commit_group;" ::: "memory");
}

__device__ __forceinline__ void mma_stepC(uint32_t st, int wm, int wn, int lane,
                                          FragC& f) {
    int lr    = lane & 15;
    int ahalf = ((lane >> 4) & 1) * 16;
    int brow  = ((lane >> 4) & 1) * 8 + (lane & 7);
    int bhalf = ((lane >> 3) & 1) * 16;
    #pragma unroll
    for (int kk = 0; kk < 4; kk++) {
        uint32_t bh[2][4];
        #pragma unroll
        for (int bt = 0; bt < 2; bt++) {
            uint32_t off = SW128((uint32_t)(wn * 32 + bt * 16 + brow) * 128 + kk * 32 + bhalf);
            LDSM_X4(bh[bt], st + C_BHI + off);
        }
        #pragma unroll
        for (int mt = 0; mt < 4; mt++) {
            uint32_t a[4];
            uint32_t off = SW128((uint32_t)(wm * 64 + mt * 16 + lr) * 128 + kk * 32 + ahalf);
            LDSM_X4(a, st + off);
            #pragma unroll
            for (int nt = 0; nt < 4; nt++) {
                int bt = nt >> 1, pp = (nt & 1) * 2;
                MMA16816(f.acc[mt][nt], a, bh[bt][pp], bh[bt][pp + 1]);
            }
        }
    }
}

__global__ void __launch_bounds__(256, 2)
conv_mma(const float* __restrict__ gamma_p,
         const float* __restrict__ beta_p,
         float* __restrict__ out) {
    extern __shared__ __align__(1024) char smem[];
    uint32_t sb = smem_u32(smem);
    int tid = threadIdx.x, wid = tid >> 5, lane = tid & 31;
    int q0     = blockIdx.x * 128;
    int cobase = blockIdx.y * 128;
    int b      = blockIdx.z;
    int wm = wid >> 2, wn = wid & 3;

    FragC f;
    #pragma unroll
    for (int mt = 0; mt < 4; mt++)
        #pragma unroll
        for (int nt = 0; nt < 4; nt++)
            #pragma unroll
            for (int r = 0; r < 4; r++) f.acc[mt][nt][r] = 0.f;

    conv_load(sb, 0, cobase, q0, b, tid);
    conv_load(sb, 1, cobase, q0, b, tid);
    for (int s = 0; s < CNSTEP; s++) {
        if (s + 1 < CNSTEP) asm volatile("cp.async.wait_group 1;" ::: "memory");
        else                asm volatile("cp.async.wait_group 0;" ::: "memory");
        __syncthreads();
        if (s + 2 < CNSTEP) conv_load(sb, s + 2, cobase, q0, b, tid);
        mma_stepC(sb + (uint32_t)(s % 3) * CSTG, wm, wn, lane, f);
    }

    // epilogue: BN + sigmoid gate; pi -> (r,c); guarded stores
    int head = (cobase >> 6) + wm;
    int qb = q0 + wn * 32;
    float inv = rsqrtf(1.0f + BN_EPS);
    float av[4][2];
    int hwv[4][2];
    #pragma unroll
    for (int nt = 0; nt < 4; nt++) {
        #pragma unroll
        for (int e = 0; e < 2; e++) {
            int qq = qb + nt * 8 + (lane & 3) * 2 + e;
            int pr = qq / 41, pc = qq - pr * 41;
            bool ok = (pc < 40 && pr < 40);
            int hw = pr * 40 + pc;
            hwv[nt][e] = ok ? hw : -1;
            av[nt][e] = ok ? attn_buf[(size_t)(b * NH + head) * HW + hw] : 0.f;
        }
    }
    #pragma unroll
    for (int mt = 0; mt < 4; mt++) {
        int r0 = cobase + wm * 64 + mt * 16 + (lane >> 2);
        float sc0 = gamma_p[r0] * inv,     bt0 = beta_p[r0];
        float sc8 = gamma_p[r0 + 8] * inv, bt8 = beta_p[r0 + 8];
        #pragma unroll
        for (int nt = 0; nt < 4; nt++) {
            #pragma unroll
            for (int e = 0; e < 2; e++) {
                int hw = hwv[nt][e];
                if (hw >= 0) {
                    out[((size_t)(b * COUT + r0)) * HW + hw]     = (f.acc[mt][nt][e]     * sc0 + bt0) * av[nt][e];
                    out[((size_t)(b * COUT + r0 + 8)) * HW + hw] = (f.acc[mt][nt][e + 2] * sc8 + bt8) * av[nt][e];
                }
            }
        }
    }
}

// =============== embed 1x1 (M=256=all E) + MMA attn: 512 thr ================
#define E_BHI  32768
#define ESTG   49152       // A 32K | B 16K
#define ENSTEP 8
#define TSH 264                          // fp16 tile row stride (halves)
#define GSH_OFF (128 * TSH)              // g region offset (halves)
#define ESMEM 109824                     // (128 + 80) * 264 * 2

__device__ __forceinline__ void embed_load(uint32_t sb, int s, int q0, int b, int tid) {
    uint32_t st = sb + (uint32_t)(s & 1) * ESTG;
    const char* a_src = (const char*)(we_h + s * 64);
    size_t xoff = ((size_t)b * PBUF + XOFF + q0) * CIN + s * 64;
    const char* b_src = (const char*)(xp_hi + xoff);
    #pragma unroll
    for (int i = 0; i < 4; i++) {        // A: 2048 cp16 (256 rows x 128B)
        int id = tid + i * 512;
        int row = id >> 3, ch = id & 7;
        cp16(st + SW128(row * 128 + ch * 16), a_src + (size_t)row * 1024 + ch * 16);
    }
    #pragma unroll
    for (int i = 0; i < 2; i++) {        // B: 1024 cp16 (128 rows x 128B)
        int id = tid + i * 512;
        int row = id >> 3, ch = id & 7;
        cp16(st + E_BHI + SW128(row * 128 + ch * 16), b_src + (size_t)row * 1024 + ch * 16);
    }
    asm volatile("cp.async.commit_group;" ::: "memory");
}

__device__ __forceinline__ void mma_stepE(uint32_t st, int wm, int wn, int lane,
                                          FragC& f) {
    int lr    = lane & 15;
    int ahalf = ((lane >> 4) & 1) * 16;
    int brow  = ((lane >> 4) & 1) * 8 + (lane & 7);
    int bhalf = ((lane >> 3) & 1) * 16;
    #pragma unroll
    for (int kk = 0; kk < 4; kk++) {
        uint32_t bh[2][4];
        #pragma unroll
        for (int bt = 0; bt < 2; bt++) {
            uint32_t off = SW128((uint32_t)(wn * 32 + bt * 16 + brow) * 128 + kk * 32 + bhalf);
            LDSM_X4(bh[bt], st + E_BHI + off);
        }
        #pragma unroll
        for (int mt = 0; mt < 4; mt++) {
            uint32_t a[4];
            uint32_t off = SW128((uint32_t)(wm * 64 + mt * 16 + lr) * 128 + kk * 32 + ahalf);
            LDSM_X4(a, st + off);
            #pragma unroll
            for (int nt = 0; nt < 4; nt++) {
                int bt = nt >> 1, pp = (nt & 1) * 2;
                MMA16816(f.acc[mt][nt], a, bh[bt][pp], bh[bt][pp + 1]);
            }
        }
    }
}

__global__ void __launch_bounds__(512, 1)
embed_attn(const float* __restrict__ gamma_e,
           const float* __restrict__ beta_e,
           const float* __restrict__ head_bias) {
    extern __shared__ __align__(1024) char smem[];
    uint32_t sb = smem_u32(smem);
    int tid = threadIdx.x, wid = tid >> 5, lane = tid & 31;
    int q0 = blockIdx.x * 128;
    int b  = blockIdx.z;
    int wm = wid >> 2, wn = wid & 3;

    FragC f;
    #pragma unroll
    for (int mt = 0; mt < 4; mt++)
        #pragma unroll
        for (int nt = 0; nt < 4; nt++)
            #pragma unroll
            for (int r = 0; r < 4; r++) f.acc[mt][nt][r] = 0.f;

    embed_load(sb, 0, q0, b, tid);
    for (int s = 0; s < ENSTEP; s++) {
        asm volatile("cp.async.wait_group 0;" ::: "memory");
        __syncthreads();
        if (s + 1 < ENSTEP) embed_load(sb, s + 1, q0, b, tid);
        mma_stepE(sb + (uint32_t)(s & 1) * ESTG, wm, wn, lane, f);
    }
    __syncthreads();   // stage buffers reused below

    // BN + write fp16 tile[q][e] (stride TSH halves)
    __half* tile = reinterpret_cast<__half*>(smem);
    __half* gsm  = tile + GSH_OFF;
    float inv = rsqrtf(1.0f + BN_EPS);
    #pragma unroll
    for (int mt = 0; mt < 4; mt++) {
        int er = wm * 64 + mt * 16 + (lane >> 2);
        float sc0 = gamma_e[er] * inv,     bt0 = beta_e[er];
        float sc8 = gamma_e[er + 8] * inv, bt8 = beta_e[er + 8];
        #pragma unroll
        for (int nt = 0; nt < 4; nt++) {
            int ql = wn * 32 + nt * 8 + (lane & 3) * 2;
            tile[ql * TSH + er]           = __float2half(f.acc[mt][nt][0] * sc0 + bt0);
            tile[(ql + 1) * TSH + er]     = __float2half(f.acc[mt][nt][1] * sc0 + bt0);
            tile[ql * TSH + er + 8]       = __float2half(f.acc[mt][nt][2] * sc8 + bt8);
            tile[(ql + 1) * TSH + er + 8] = __float2half(f.acc[mt][nt][3] * sc8 + bt8);
        }
    }
    // stage g[b] as fp16: gsm[n*TSH + e]
    {
        const float* gsrc = g_buf + (size_t)b * NTOK * EE;
        for (int i = tid; i < NTOK * EE / 4; i += 512) {
            int n = i >> 6, eq = (i & 63) * 4;
            float4 v = reinterpret_cast<const float4*>(gsrc)[i];
            __half h4[4] = {__float2half(v.x), __float2half(v.y),
                            __float2half(v.z), __float2half(v.w)};
            *reinterpret_cast<uint2*>(&gsm[n * TSH + eq]) = *reinterpret_cast<const uint2*>(h4);
        }
    }
    __syncthreads();

    // ---- MMA attention scores: warp = (head m, q-half qh) ----
    int m  = wid >> 1;
    int qh = wid & 1;
    int qb = qh * 64;
    uint32_t tb = sb;                // tile base (bytes)
    uint32_t gb = sb + GSH_OFF * 2;  // g base (bytes)
    int lr = lane & 15;
    int ah16 = ((lane >> 4) & 1) * 16;          // A k-half byte offset
    int brow = ((lane >> 4) & 1) * 8 + (lane & 7);
    int bh16 = ((lane >> 3) & 1) * 16;          // B k-half byte offset

    uint32_t a[4][2][4];
    #pragma unroll
    for (int mt = 0; mt < 4; mt++)
        #pragma unroll
        for (int kk = 0; kk < 2; kk++) {
            uint32_t addr = tb + (uint32_t)(qb + mt * 16 + lr) * (TSH * 2)
                          + (m * 32 + kk * 16) * 2 + ah16;
            LDSM_X4(a[mt][kk], addr);
        }

    float rmax[4][2];
    #pragma unroll
    for (int mt = 0; mt < 4; mt++) { rmax[mt][0] = -3.4e38f; rmax[mt][1] = -3.4e38f; }

    #pragma unroll
    for (int nt16 = 0; nt16 < 5; nt16++) {
        uint32_t b0[4], b1[4];
        uint32_t baddr = gb + (uint32_t)(nt16 * 16 + brow) * (TSH * 2) + m * 32 * 2 + bh16;
        LDSM_X4(b0, baddr);
        LDSM_X4(b1, baddr + 32);      // kk=1: +16 halves
        #pragma unroll
        for (int sub = 0; sub < 2; sub++) {
            #pragma unroll
            for (int mt = 0; mt < 4; mt++) {
                float acc[4] = {0.f, 0.f, 0.f, 0.f};
                MMA16816(acc, a[mt][0], b0[sub * 2], b0[sub * 2 + 1]);
                MMA16816(acc, a[mt][1], b1[sub * 2], b1[sub * 2 + 1]);
                rmax[mt][0] = fmaxf(rmax[mt][0], fmaxf(acc[0], acc[1]));
                rmax[mt][1] = fmaxf(rmax[mt][1], fmaxf(acc[2], acc[3]));
            }
        }
    }

    float hb = head_bias[m];
    #pragma unroll
    for (int mt = 0; mt < 4; mt++) {
        #pragma unroll
        for (int r01 = 0; r01 < 2; r01++) {
            float v = rmax[mt][r01];
            v = fmaxf(v, __shfl_xor_sync(0xFFFFFFFFu, v, 1));
            v = fmaxf(v, __shfl_xor_sync(0xFFFFFFFFu, v, 2));
            if ((lane & 3) == 0) {
                int qq = q0 + qb + mt * 16 + (lane >> 2) + r01 * 8;
                int pr = qq / 41, pc = qq - pr * 41;
                if (pc < 40 && pr < 40) {
                    float aa = v * 0.17677669529663687f + hb;
                    float s = 1.0f / (1.0f + expf(-aa));
                    attn_buf[(size_t)(b * NH + m) * HW + pr * 40 + pc] = s;
                }
            }
        }
    }
}

extern "C" void kernel_launch(void* const* d_in, const int* in_sizes, int n_in,
                              void* d_out, int out_size) {
    const float* x         = (const float*)d_in[0];
    const float* guide     = (const float*)d_in[1];
    const float* We        = (const float*)d_in[2];
    const float* gamma_e   = (const float*)d_in[3];
    const float* beta_e    = (const float*)d_in[4];
    const float* Wg        = (const float*)d_in[5];
    const float* bg        = (const float*)d_in[6];
    const float* head_bias = (const float*)d_in[7];
    const float* Wp        = (const float*)d_in[8];
    const float* gamma_p   = (const float*)d_in[9];
    const float* beta_p    = (const float*)d_in[10];
    float* out = (float*)d_out;

    xprep<<<dim3(40, 8, 16), 256>>>(x);
    wprep<<<768, 256>>>(Wp, We);
    guide_gemm<<<dim3(40, 8), 256>>>(guide, Wg, bg);
    cudaFuncSetAttribute(embed_attn, cudaFuncAttributeMaxDynamicSharedMemorySize, ESMEM);
    embed_attn<<<dim3(13, 1, 16), 512, ESMEM>>>(gamma_e, beta_e, head_bias);
    cudaFuncSetAttribute(conv_mma, cudaFuncAttributeMaxDynamicSharedMemorySize, CSMEM);
    conv_mma<<<dim3(13, 4, 16), 256, CSMEM>>>(gamma_p, beta_p, out);
}

// round 12
// speedup vs baseline: 1.2516x; 1.0189x over previous
#include <cuda_runtime.h>
#include <cuda_fp16.h>
#include <cstdint>

#define BB   16
#define CIN  512
#define HH   40
#define WW   40
#define HW   1600
#define NTOK 80
#define CG   512
#define EE   256
#define COUT 512
#define NH   8
#define HC   32
#define BN_EPS 1e-3f
// 41-stride shared-pad pixel space: pi = r*41 + c, slot c=40 of each row = shared pad
#define PBUF 1792
#define XOFF 64

// ------------------------------ scratch (device globals) -------------------
__device__ float g_buf[BB * NTOK * EE];
__device__ float attn_buf[BB * NH * HW];
__device__ __align__(256) __half xp_hi[(size_t)BB * PBUF * CIN];
__device__ __align__(256) __half wk_h[(size_t)9 * COUT * CIN];
__device__ __align__(256) __half we_h[EE * CIN];

// ------------------------------ helpers ------------------------------------
__device__ __forceinline__ uint32_t smem_u32(const void* p) {
    uint32_t a;
    asm("{ .reg .u64 t; cvta.to.shared.u64 t, %1; cvt.u32.u64 %0, t; }" : "=r"(a) : "l"(p));
    return a;
}
#define SW128(off) ((off) ^ (((off) >> 3) & 0x70))

__device__ __forceinline__ void cp16(uint32_t dst, const void* src) {
    asm volatile("cp.async.cg.shared.global [%0], [%1], 16;" :: "r"(dst), "l"(src));
}

#define LDSM_X4(r, a) \
    asm volatile("ldmatrix.sync.aligned.m8n8.x4.shared.b16 {%0,%1,%2,%3}, [%4];" \
        : "=r"((r)[0]), "=r"((r)[1]), "=r"((r)[2]), "=r"((r)[3]) : "r"(a))

#define MMA16816(d, a, b0, b1) \
    asm volatile("mma.sync.aligned.m16n8k16.row.col.f32.f16.f16.f32 " \
        "{%0,%1,%2,%3}, {%4,%5,%6,%7}, {%8,%9}, {%0,%1,%2,%3};" \
        : "+f"((d)[0]), "+f"((d)[1]), "+f"((d)[2]), "+f"((d)[3]) \
        : "r"((a)[0]), "r"((a)[1]), "r"((a)[2]), "r"((a)[3]), "r"(b0), "r"(b1))

// -------- merged prep: Wp -> wk_h, We -> we_h, guide FC -> g_buf ------------
__global__ void prep_wg(const float* __restrict__ Wp, const float* __restrict__ We,
                        const float* __restrict__ guide, const float* __restrict__ Wg,
                        const float* __restrict__ bg) {
    int bid = blockIdx.x;
    if (bid < COUT) {
        int co = bid;
        for (int ci = threadIdx.x; ci < CIN; ci += 256) {
            const float* src = Wp + ((size_t)co * CIN + ci) * 9;
            #pragma unroll
            for (int k = 0; k < 9; k++)
                wk_h[((size_t)k * COUT + co) * CIN + ci] = __float2half(src[k]);
        }
        return;
    }
    if (bid < COUT + EE) {
        int e = bid - COUT;
        for (int ci = threadIdx.x; ci < CIN; ci += 256)
            we_h[(size_t)e * CIN + ci] = __float2half(We[(size_t)e * CIN + ci]);
        return;
    }
    // guide FC: 320 blocks (40 x 8)
    int gb = bid - COUT - EE;
    int row0 = (gb % 40) * 32;
    int col0 = (gb / 40) * 32;
    __shared__ float As[32][33];
    __shared__ float Bs[32][33];
    int tid = threadIdx.x;
    int tx = tid & 31, ty = tid >> 5;
    float acc[4] = {0.f, 0.f, 0.f, 0.f};
    for (int kc = 0; kc < CG; kc += 32) {
        int r = tid >> 3, kq = (tid & 7) * 4;
        float4 a4 = *reinterpret_cast<const float4*>(&guide[(size_t)(row0 + r) * CG + kc + kq]);
        As[r][kq] = a4.x; As[r][kq + 1] = a4.y; As[r][kq + 2] = a4.z; As[r][kq + 3] = a4.w;
        float4 b4 = *reinterpret_cast<const float4*>(&Wg[(size_t)(col0 + r) * CG + kc + kq]);
        Bs[r][kq] = b4.x; Bs[r][kq + 1] = b4.y; Bs[r][kq + 2] = b4.z; Bs[r][kq + 3] = b4.w;
        __syncthreads();
        #pragma unroll
        for (int k = 0; k < 32; k++) {
            float bv = Bs[tx][k];
            #pragma unroll
            for (int rr = 0; rr < 4; rr++)
                acc[rr] += As[ty + 8 * rr][k] * bv;
        }
        __syncthreads();
    }
    float bias = bg[col0 + tx];
    #pragma unroll
    for (int rr = 0; rr < 4; rr++)
        g_buf[(size_t)(row0 + ty + 8 * rr) * EE + col0 + tx] = acc[rr] + bias;
}

// x(r,c) -> padded fp16 at pi = r*41 + c; vectorized 16B stores; pads included
__global__ void xprep(const float* __restrict__ x) {
    __shared__ float s[64][41];
    int r  = blockIdx.x;
    int cc = blockIdx.y * 64;
    int b  = blockIdx.z;
    for (int idx = threadIdx.x; idx < 64 * 40; idx += 256) {
        int ci = idx / 40, c = idx % 40;
        s[ci][c] = x[((size_t)(b * CIN + cc + ci)) * HW + r * WW + c];
    }
    __syncthreads();
    for (int idx = threadIdx.x; idx < 41 * 8; idx += 256) {
        int c = idx >> 3, cg = idx & 7;
        __half h8[8];
        #pragma unroll
        for (int j = 0; j < 8; j++)
            h8[j] = __float2half((c < 40) ? s[cg * 8 + j][c] : 0.f);
        size_t off = ((size_t)b * PBUF + XOFF + r * 41 + c) * CIN + cc + cg * 8;
        *reinterpret_cast<uint4*>(&xp_hi[off]) = *reinterpret_cast<const uint4*>(h8);
    }
    if (r == 0) {
        uint4 z = {0, 0, 0, 0};
        for (int idx = threadIdx.x; idx < 152 * 8; idx += 256) {
            int sl = idx >> 3, cg = idx & 7;
            int slot = (sl < XOFF) ? sl : (XOFF + 1640 + sl - XOFF);
            *reinterpret_cast<uint4*>(&xp_hi[((size_t)b * PBUF + slot) * CIN + cc + cg * 8]) = z;
        }
    }
}

// =============== conv: CTA 128(M) x 128(N), 8 warps 64x32, 2 CTAs/SM ========
#define C_BHI  16384
#define CSTG   32768       // A 16K | B 16K
#define CSMEM  98304       // 3 stages
#define CNSTEP 72

struct FragC { float acc[4][4][4]; };

__device__ __forceinline__ void conv_load(uint32_t sb, int s, int cobase,
                                          int q0, int b, int tid) {
    int k = s >> 3, cc = s & 7;
    int kh = k / 3, kw = k - kh * 3;
    uint32_t st = sb + (uint32_t)(s % 3) * CSTG;
    const char* a_src = (const char*)(wk_h + ((size_t)k * COUT + cobase) * CIN + cc * 64);
    size_t xoff = ((size_t)b * PBUF + XOFF + q0 + (kh - 1) * 41 + (kw - 1)) * CIN + cc * 64;
    const char* b_src = (const char*)(xp_hi + xoff);
    #pragma unroll
    for (int i = 0; i < 4; i++) {
        int id = tid + i * 256;
        int row = id >> 3, ch = id & 7;
        cp16(st + SW128(row * 128 + ch * 16), a_src + (size_t)row * 1024 + ch * 16);
    }
    #pragma unroll
    for (int i = 0; i < 4; i++) {
        int id = tid + i * 256;
        int row = id >> 3, ch = id & 7;
        cp16(st + C_BHI + SW128(row * 128 + ch * 16), b_src + (size_t)row * 1024 + ch * 16);
    }
    asm volatile("cp.async.commit_group;" ::: "memory");
}

// B fragments for the whole step hoisted up front: larger LDSM->MMA distance
__device__ __forceinline__ void mma_stepC(uint32_t st, int wm, int wn, int lane,
                                          FragC& f) {
    int lr    = lane & 15;
    int ahalf = ((lane >> 4) & 1) * 16;
    int brow  = ((lane >> 4) & 1) * 8 + (lane & 7);
    int bhalf = ((lane >> 3) & 1) * 16;
    uint32_t bh[4][2][4];
    #pragma unroll
    for (int kk = 0; kk < 4; kk++)
        #pragma unroll
        for (int bt = 0; bt < 2; bt++) {
            uint32_t off = SW128((uint32_t)(wn * 32 + bt * 16 + brow) * 128 + kk * 32 + bhalf);
            LDSM_X4(bh[kk][bt], st + C_BHI + off);
        }
    #pragma unroll
    for (int kk = 0; kk < 4; kk++) {
        #pragma unroll
        for (int mt = 0; mt < 4; mt++) {
            uint32_t a[4];
            uint32_t off = SW128((uint32_t)(wm * 64 + mt * 16 + lr) * 128 + kk * 32 + ahalf);
            LDSM_X4(a, st + off);
            #pragma unroll
            for (int nt = 0; nt < 4; nt++) {
                int bt = nt >> 1, pp = (nt & 1) * 2;
                MMA16816(f.acc[mt][nt], a, bh[kk][bt][pp], bh[kk][bt][pp + 1]);
            }
        }
    }
}

__global__ void __launch_bounds__(256, 2)
conv_mma(const float* __restrict__ gamma_p,
         const float* __restrict__ beta_p,
         float* __restrict__ out) {
    extern __shared__ __align__(1024) char smem[];
    uint32_t sb = smem_u32(smem);
    int tid = threadIdx.x, wid = tid >> 5, lane = tid & 31;
    int q0     = blockIdx.x * 128;
    int cobase = blockIdx.y * 128;
    int b      = blockIdx.z;
    int wm = wid >> 2, wn = wid & 3;

    FragC f;
    #pragma unroll
    for (int mt = 0; mt < 4; mt++)
        #pragma unroll
        for (int nt = 0; nt < 4; nt++)
            #pragma unroll
            for (int r = 0; r < 4; r++) f.acc[mt][nt][r] = 0.f;

    conv_load(sb, 0, cobase, q0, b, tid);
    conv_load(sb, 1, cobase, q0, b, tid);
    for (int s = 0; s < CNSTEP; s++) {
        if (s + 1 < CNSTEP) asm volatile("cp.async.wait_group 1;" ::: "memory");
        else                asm volatile("cp.async.wait_group 0;" ::: "memory");
        __syncthreads();
        if (s + 2 < CNSTEP) conv_load(sb, s + 2, cobase, q0, b, tid);
        mma_stepC(sb + (uint32_t)(s % 3) * CSTG, wm, wn, lane, f);
    }

    // epilogue: BN + sigmoid gate; pi -> (r,c); guarded stores
    int head = (cobase >> 6) + wm;
    int qb = q0 + wn * 32;
    float inv = rsqrtf(1.0f + BN_EPS);
    float av[4][2];
    int hwv[4][2];
    #pragma unroll
    for (int nt = 0; nt < 4; nt++) {
        #pragma unroll
        for (int e = 0; e < 2; e++) {
            int qq = qb + nt * 8 + (lane & 3) * 2 + e;
            int pr = qq / 41, pc = qq - pr * 41;
            bool ok = (pc < 40 && pr < 40);
            int hw = pr * 40 + pc;
            hwv[nt][e] = ok ? hw : -1;
            av[nt][e] = ok ? attn_buf[(size_t)(b * NH + head) * HW + hw] : 0.f;
        }
    }
    #pragma unroll
    for (int mt = 0; mt < 4; mt++) {
        int r0 = cobase + wm * 64 + mt * 16 + (lane >> 2);
        float sc0 = gamma_p[r0] * inv,     bt0 = beta_p[r0];
        float sc8 = gamma_p[r0 + 8] * inv, bt8 = beta_p[r0 + 8];
        #pragma unroll
        for (int nt = 0; nt < 4; nt++) {
            #pragma unroll
            for (int e = 0; e < 2; e++) {
                int hw = hwv[nt][e];
                if (hw >= 0) {
                    out[((size_t)(b * COUT + r0)) * HW + hw]     = (f.acc[mt][nt][e]     * sc0 + bt0) * av[nt][e];
                    out[((size_t)(b * COUT + r0 + 8)) * HW + hw] = (f.acc[mt][nt][e + 2] * sc8 + bt8) * av[nt][e];
                }
            }
        }
    }
}

// =============== embed 1x1 (M=256=all E) + MMA attn: 512 thr ================
#define E_BHI  32768
#define ESTG   49152       // A 32K | B 16K
#define ENSTEP 8
#define TSH 264                          // fp16 tile row stride (halves)
#define GSH_OFF (128 * TSH)              // g region offset (halves)
#define ESMEM 109824                     // (128 + 80) * 264 * 2

__device__ __forceinline__ void embed_load(uint32_t sb, int s, int q0, int b, int tid) {
    uint32_t st = sb + (uint32_t)(s & 1) * ESTG;
    const char* a_src = (const char*)(we_h + s * 64);
    size_t xoff = ((size_t)b * PBUF + XOFF + q0) * CIN + s * 64;
    const char* b_src = (const char*)(xp_hi + xoff);
    #pragma unroll
    for (int i = 0; i < 4; i++) {
        int id = tid + i * 512;
        int row = id >> 3, ch = id & 7;
        cp16(st + SW128(row * 128 + ch * 16), a_src + (size_t)row * 1024 + ch * 16);
    }
    #pragma unroll
    for (int i = 0; i < 2; i++) {
        int id = tid + i * 512;
        int row = id >> 3, ch = id & 7;
        cp16(st + E_BHI + SW128(row * 128 + ch * 16), b_src + (size_t)row * 1024 + ch * 16);
    }
    asm volatile("cp.async.commit_group;" ::: "memory");
}

__device__ __forceinline__ void mma_stepE(uint32_t st, int wm, int wn, int lane,
                                          FragC& f) {
    int lr    = lane & 15;
    int ahalf = ((lane >> 4) & 1) * 16;
    int brow  = ((lane >> 4) & 1) * 8 + (lane & 7);
    int bhalf = ((lane >> 3) & 1) * 16;
    uint32_t bh[4][2][4];
    #pragma unroll
    for (int kk = 0; kk < 4; kk++)
        #pragma unroll
        for (int bt = 0; bt < 2; bt++) {
            uint32_t off = SW128((uint32_t)(wn * 32 + bt * 16 + brow) * 128 + kk * 32 + bhalf);
            LDSM_X4(bh[kk][bt], st + E_BHI + off);
        }
    #pragma unroll
    for (int kk = 0; kk < 4; kk++) {
        #pragma unroll
        for (int mt = 0; mt < 4; mt++) {
            uint32_t a[4];
            uint32_t off = SW128((uint32_t)(wm * 64 + mt * 16 + lr) * 128 + kk * 32 + ahalf);
            LDSM_X4(a, st + off);
            #pragma unroll
            for (int nt = 0; nt < 4; nt++) {
                int bt = nt >> 1, pp = (nt & 1) * 2;
                MMA16816(f.acc[mt][nt], a, bh[kk][bt][pp], bh[kk][bt][pp + 1]);
            }
        }
    }
}

__global__ void __launch_bounds__(512, 1)
embed_attn(const float* __restrict__ gamma_e,
           const float* __restrict__ beta_e,
           const float* __restrict__ head_bias) {
    extern __shared__ __align__(1024) char smem[];
    uint32_t sb = smem_u32(smem);
    int tid = threadIdx.x, wid = tid >> 5, lane = tid & 31;
    int q0 = blockIdx.x * 128;
    int b  = blockIdx.z;
    int wm = wid >> 2, wn = wid & 3;

    FragC f;
    #pragma unroll
    for (int mt = 0; mt < 4; mt++)
        #pragma unroll
        for (int nt = 0; nt < 4; nt++)
            #pragma unroll
            for (int r = 0; r < 4; r++) f.acc[mt][nt][r] = 0.f;

    embed_load(sb, 0, q0, b, tid);
    for (int s = 0; s < ENSTEP; s++) {
        asm volatile("cp.async.wait_group 0;" ::: "memory");
        __syncthreads();
        if (s + 1 < ENSTEP) embed_load(sb, s + 1, q0, b, tid);
        mma_stepE(sb + (uint32_t)(s & 1) * ESTG, wm, wn, lane, f);
    }
    __syncthreads();   // stage buffers reused below

    // BN + write fp16 tile[q][e] (stride TSH halves)
    __half* tile = reinterpret_cast<__half*>(smem);
    __half* gsm  = tile + GSH_OFF;
    float inv = rsqrtf(1.0f + BN_EPS);
    #pragma unroll
    for (int mt = 0; mt < 4; mt++) {
        int er = wm * 64 + mt * 16 + (lane >> 2);
        float sc0 = gamma_e[er] * inv,     bt0 = beta_e[er];
        float sc8 = gamma_e[er + 8] * inv, bt8 = beta_e[er + 8];
        #pragma unroll
        for (int nt = 0; nt < 4; nt++) {
            int ql = wn * 32 + nt * 8 + (lane & 3) * 2;
            tile[ql * TSH + er]           = __float2half(f.acc[mt][nt][0] * sc0 + bt0);
            tile[(ql + 1) * TSH + er]     = __float2half(f.acc[mt][nt][1] * sc0 + bt0);
            tile[ql * TSH + er + 8]       = __float2half(f.acc[mt][nt][2] * sc8 + bt8);
            tile[(ql + 1) * TSH + er + 8] = __float2half(f.acc[mt][nt][3] * sc8 + bt8);
        }
    }
    // stage g[b] as fp16: gsm[n*TSH + e]
    {
        const float* gsrc = g_buf + (size_t)b * NTOK * EE;
        for (int i = tid; i < NTOK * EE / 4; i += 512) {
            int n = i >> 6, eq = (i & 63) * 4;
            float4 v = reinterpret_cast<const float4*>(gsrc)[i];
            __half h4[4] = {__float2half(v.x), __float2half(v.y),
                            __float2half(v.z), __float2half(v.w)};
            *reinterpret_cast<uint2*>(&gsm[n * TSH + eq]) = *reinterpret_cast<const uint2*>(h4);
        }
    }
    __syncthreads();

    // ---- MMA attention scores: warp = (head m, q-half qh) ----
    int m  = wid >> 1;
    int qh = wid & 1;
    int qb = qh * 64;
    uint32_t tb = sb;
    uint32_t gb = sb + GSH_OFF * 2;
    int lr = lane & 15;
    int ah16 = ((lane >> 4) & 1) * 16;
    int brow = ((lane >> 4) & 1) * 8 + (lane & 7);
    int bh16 = ((lane >> 3) & 1) * 16;

    uint32_t a[4][2][4];
    #pragma unroll
    for (int mt = 0; mt < 4; mt++)
        #pragma unroll
        for (int kk = 0; kk < 2; kk++) {
            uint32_t addr = tb + (uint32_t)(qb + mt * 16 + lr) * (TSH * 2)
                          + (m * 32 + kk * 16) * 2 + ah16;
            LDSM_X4(a[mt][kk], addr);
        }

    float rmax[4][2];
    #pragma unroll
    for (int mt = 0; mt < 4; mt++) { rmax[mt][0] = -3.4e38f; rmax[mt][1] = -3.4e38f; }

    #pragma unroll
    for (int nt16 = 0; nt16 < 5; nt16++) {
        uint32_t b0[4], b1[4];
        uint32_t baddr = gb + (uint32_t)(nt16 * 16 + brow) * (TSH * 2) + m * 32 * 2 + bh16;
        LDSM_X4(b0, baddr);
        LDSM_X4(b1, baddr + 32);
        #pragma unroll
        for (int sub = 0; sub < 2; sub++) {
            #pragma unroll
            for (int mt = 0; mt < 4; mt++) {
                float acc[4] = {0.f, 0.f, 0.f, 0.f};
                MMA16816(acc, a[mt][0], b0[sub * 2], b0[sub * 2 + 1]);
                MMA16816(acc, a[mt][1], b1[sub * 2], b1[sub * 2 + 1]);
                rmax[mt][0] = fmaxf(rmax[mt][0], fmaxf(acc[0], acc[1]));
                rmax[mt][1] = fmaxf(rmax[mt][1], fmaxf(acc[2], acc[3]));
            }
        }
    }

    float hb = head_bias[m];
    #pragma unroll
    for (int mt = 0; mt < 4; mt++) {
        #pragma unroll
        for (int r01 = 0; r01 < 2; r01++) {
            float v = rmax[mt][r01];
            v = fmaxf(v, __shfl_xor_sync(0xFFFFFFFFu, v, 1));
            v = fmaxf(v, __shfl_xor_sync(0xFFFFFFFFu, v, 2));
            if ((lane & 3) == 0) {
                int qq = q0 + qb + mt * 16 + (lane >> 2) + r01 * 8;
                int pr = qq / 41, pc = qq - pr * 41;
                if (pc < 40 && pr < 40) {
                    float aa = v * 0.17677669529663687f + hb;
                    float s = 1.0f / (1.0f + __expf(-aa));
                    attn_buf[(size_t)(b * NH + m) * HW + pr * 40 + pc] = s;
                }
            }
        }
    }
}

extern "C" void kernel_launch(void* const* d_in, const int* in_sizes, int n_in,
                              void* d_out, int out_size) {
    const float* x         = (const float*)d_in[0];
    const float* guide     = (const float*)d_in[1];
    const float* We        = (const float*)d_in[2];
    const float* gamma_e   = (const float*)d_in[3];
    const float* beta_e    = (const float*)d_in[4];
    const float* Wg        = (const float*)d_in[5];
    const float* bg        = (const float*)d_in[6];
    const float* head_bias = (const float*)d_in[7];
    const float* Wp        = (const float*)d_in[8];
    const float* gamma_p   = (const float*)d_in[9];
    const float* beta_p    = (const float*)d_in[10];
    float* out = (float*)d_out;

    xprep<<<dim3(40, 8, 16), 256>>>(x);
    prep_wg<<<COUT + EE + 320, 256>>>(Wp, We, guide, Wg, bg);
    cudaFuncSetAttribute(embed_attn, cudaFuncAttributeMaxDynamicSharedMemorySize, ESMEM);
    embed_attn<<<dim3(13, 1, 16), 512, ESMEM>>>(gamma_e, beta_e, head_bias);
    cudaFuncSetAttribute(conv_mma, cudaFuncAttributeMaxDynamicSharedMemorySize, CSMEM);
    conv_mma<<<dim3(13, 4, 16), 256, CSMEM>>>(gamma_p, beta_p, out);
}

// round 13
// speedup vs baseline: 1.2660x; 1.0115x over previous
#include <cuda_runtime.h>
#include <cuda_fp16.h>
#include <cstdint>

#define BB   16
#define CIN  512
#define HH   40
#define WW   40
#define HW   1600
#define NTOK 80
#define CG   512
#define EE   256
#define COUT 512
#define NH   8
#define HC   32
#define BN_EPS 1e-3f
// 41-stride shared-pad pixel space: pi = r*41 + c, slot c=40 of each row = shared pad
#define PBUF 1792
#define XOFF 64

// ------------------------------ scratch (device globals) -------------------
__device__ float g_buf[BB * NTOK * EE];
__device__ float attn_buf[BB * NH * HW];
__device__ __align__(256) __half xp_hi[(size_t)BB * PBUF * CIN];
__device__ __align__(256) __half wk_h[(size_t)9 * COUT * CIN];
__device__ __align__(256) __half we_h[EE * CIN];

// ------------------------------ helpers ------------------------------------
__device__ __forceinline__ uint32_t smem_u32(const void* p) {
    uint32_t a;
    asm("{ .reg .u64 t; cvta.to.shared.u64 t, %1; cvt.u32.u64 %0, t; }" : "=r"(a) : "l"(p));
    return a;
}
#define SW128(off) ((off) ^ (((off) >> 3) & 0x70))

__device__ __forceinline__ void cp16(uint32_t dst, const void* src) {
    asm volatile("cp.async.cg.shared.global [%0], [%1], 16;" :: "r"(dst), "l"(src));
}

#define LDSM_X4(r, a) \
    asm volatile("ldmatrix.sync.aligned.m8n8.x4.shared.b16 {%0,%1,%2,%3}, [%4];" \
        : "=r"((r)[0]), "=r"((r)[1]), "=r"((r)[2]), "=r"((r)[3]) : "r"(a))

#define MMA16816(d, a, b0, b1) \
    asm volatile("mma.sync.aligned.m16n8k16.row.col.f32.f16.f16.f32 " \
        "{%0,%1,%2,%3}, {%4,%5,%6,%7}, {%8,%9}, {%0,%1,%2,%3};" \
        : "+f"((d)[0]), "+f"((d)[1]), "+f"((d)[2]), "+f"((d)[3]) \
        : "r"((a)[0]), "r"((a)[1]), "r"((a)[2]), "r"((a)[3]), "r"(b0), "r"(b1))

// -------- merged prep: Wp -> wk_h, We -> we_h, guide FC -> g_buf ------------
__global__ void prep_wg(const float* __restrict__ Wp, const float* __restrict__ We,
                        const float* __restrict__ guide, const float* __restrict__ Wg,
                        const float* __restrict__ bg) {
    int bid = blockIdx.x;
    if (bid < COUT) {
        int co = bid;
        for (int ci = threadIdx.x; ci < CIN; ci += 256) {
            const float* src = Wp + ((size_t)co * CIN + ci) * 9;
            #pragma unroll
            for (int k = 0; k < 9; k++)
                wk_h[((size_t)k * COUT + co) * CIN + ci] = __float2half(src[k]);
        }
        return;
    }
    if (bid < COUT + EE) {
        int e = bid - COUT;
        for (int ci = threadIdx.x; ci < CIN; ci += 256)
            we_h[(size_t)e * CIN + ci] = __float2half(We[(size_t)e * CIN + ci]);
        return;
    }
    int gb = bid - COUT - EE;
    int row0 = (gb % 40) * 32;
    int col0 = (gb / 40) * 32;
    __shared__ float As[32][33];
    __shared__ float Bs[32][33];
    int tid = threadIdx.x;
    int tx = tid & 31, ty = tid >> 5;
    float acc[4] = {0.f, 0.f, 0.f, 0.f};
    for (int kc = 0; kc < CG; kc += 32) {
        int r = tid >> 3, kq = (tid & 7) * 4;
        float4 a4 = *reinterpret_cast<const float4*>(&guide[(size_t)(row0 + r) * CG + kc + kq]);
        As[r][kq] = a4.x; As[r][kq + 1] = a4.y; As[r][kq + 2] = a4.z; As[r][kq + 3] = a4.w;
        float4 b4 = *reinterpret_cast<const float4*>(&Wg[(size_t)(col0 + r) * CG + kc + kq]);
        Bs[r][kq] = b4.x; Bs[r][kq + 1] = b4.y; Bs[r][kq + 2] = b4.z; Bs[r][kq + 3] = b4.w;
        __syncthreads();
        #pragma unroll
        for (int k = 0; k < 32; k++) {
            float bv = Bs[tx][k];
            #pragma unroll
            for (int rr = 0; rr < 4; rr++)
                acc[rr] += As[ty + 8 * rr][k] * bv;
        }
        __syncthreads();
    }
    float bias = bg[col0 + tx];
    #pragma unroll
    for (int rr = 0; rr < 4; rr++)
        g_buf[(size_t)(row0 + ty + 8 * rr) * EE + col0 + tx] = acc[rr] + bias;
}

// x(r,c) -> padded fp16 at pi = r*41 + c; vectorized 16B stores; pads included
__global__ void xprep(const float* __restrict__ x) {
    __shared__ float s[64][41];
    int r  = blockIdx.x;
    int cc = blockIdx.y * 64;
    int b  = blockIdx.z;
    for (int idx = threadIdx.x; idx < 64 * 40; idx += 256) {
        int ci = idx / 40, c = idx % 40;
        s[ci][c] = x[((size_t)(b * CIN + cc + ci)) * HW + r * WW + c];
    }
    __syncthreads();
    for (int idx = threadIdx.x; idx < 41 * 8; idx += 256) {
        int c = idx >> 3, cg = idx & 7;
        __half h8[8];
        #pragma unroll
        for (int j = 0; j < 8; j++)
            h8[j] = __float2half((c < 40) ? s[cg * 8 + j][c] : 0.f);
        size_t off = ((size_t)b * PBUF + XOFF + r * 41 + c) * CIN + cc + cg * 8;
        *reinterpret_cast<uint4*>(&xp_hi[off]) = *reinterpret_cast<const uint4*>(h8);
    }
    if (r == 0) {
        uint4 z = {0, 0, 0, 0};
        for (int idx = threadIdx.x; idx < 152 * 8; idx += 256) {
            int sl = idx >> 3, cg = idx & 7;
            int slot = (sl < XOFF) ? sl : (XOFF + 1640 + sl - XOFF);
            *reinterpret_cast<uint4*>(&xp_hi[((size_t)b * PBUF + slot) * CIN + cc + cg * 8]) = z;
        }
    }
}

// =============== conv: CTA 128(M) x 128(N), 8 warps 64x32, 2 CTAs/SM ========
#define C_BHI  16384
#define CSTG   32768       // A 16K | B 16K
#define CSMEM  98304       // 3 stages
#define CNSTEP 72

struct FragC { float acc[4][4][4]; };

__device__ __forceinline__ void conv_load(uint32_t sb, int s, int cobase,
                                          int q0, int b, int tid) {
    int k = s >> 3, cc = s & 7;
    int kh = k / 3, kw = k - kh * 3;
    uint32_t st = sb + (uint32_t)(s % 3) * CSTG;
    const char* a_src = (const char*)(wk_h + ((size_t)k * COUT + cobase) * CIN + cc * 64);
    size_t xoff = ((size_t)b * PBUF + XOFF + q0 + (kh - 1) * 41 + (kw - 1)) * CIN + cc * 64;
    const char* b_src = (const char*)(xp_hi + xoff);
    #pragma unroll
    for (int i = 0; i < 4; i++) {
        int id = tid + i * 256;
        int row = id >> 3, ch = id & 7;
        cp16(st + SW128(row * 128 + ch * 16), a_src + (size_t)row * 1024 + ch * 16);
    }
    #pragma unroll
    for (int i = 0; i < 4; i++) {
        int id = tid + i * 256;
        int row = id >> 3, ch = id & 7;
        cp16(st + C_BHI + SW128(row * 128 + ch * 16), b_src + (size_t)row * 1024 + ch * 16);
    }
    asm volatile("cp.async.commit_group;" ::: "memory");
}

__device__ __forceinline__ void mma_stepC(uint32_t st, int wm, int wn, int lane,
                                          FragC& f) {
    int lr    = lane & 15;
    int ahalf = ((lane >> 4) & 1) * 16;
    int brow  = ((lane >> 4) & 1) * 8 + (lane & 7);
    int bhalf = ((lane >> 3) & 1) * 16;
    uint32_t bh[4][2][4];
    #pragma unroll
    for (int kk = 0; kk < 4; kk++)
        #pragma unroll
        for (int bt = 0; bt < 2; bt++) {
            uint32_t off = SW128((uint32_t)(wn * 32 + bt * 16 + brow) * 128 + kk * 32 + bhalf);
            LDSM_X4(bh[kk][bt], st + C_BHI + off);
        }
    #pragma unroll
    for (int kk = 0; kk < 4; kk++) {
        #pragma unroll
        for (int mt = 0; mt < 4; mt++) {
            uint32_t a[4];
            uint32_t off = SW128((uint32_t)(wm * 64 + mt * 16 + lr) * 128 + kk * 32 + ahalf);
            LDSM_X4(a, st + off);
            #pragma unroll
            for (int nt = 0; nt < 4; nt++) {
                int bt = nt >> 1, pp = (nt & 1) * 2;
                MMA16816(f.acc[mt][nt], a, bh[kk][bt][pp], bh[kk][bt][pp + 1]);
            }
        }
    }
}

__global__ void __launch_bounds__(256, 2)
conv_mma(const float* __restrict__ gamma_p,
         const float* __restrict__ beta_p,
         float* __restrict__ out) {
    extern __shared__ __align__(1024) char smem[];
    uint32_t sb = smem_u32(smem);
    int tid = threadIdx.x, wid = tid >> 5, lane = tid & 31;
    int q0     = blockIdx.x * 128;
    int cobase = blockIdx.y * 128;
    int b      = blockIdx.z;
    int wm = wid >> 2, wn = wid & 3;

    FragC f;
    #pragma unroll
    for (int mt = 0; mt < 4; mt++)
        #pragma unroll
        for (int nt = 0; nt < 4; nt++)
            #pragma unroll
            for (int r = 0; r < 4; r++) f.acc[mt][nt][r] = 0.f;

    conv_load(sb, 0, cobase, q0, b, tid);
    conv_load(sb, 1, cobase, q0, b, tid);
    for (int s = 0; s < CNSTEP; s++) {
        if (s + 1 < CNSTEP) asm volatile("cp.async.wait_group 1;" ::: "memory");
        else                asm volatile("cp.async.wait_group 0;" ::: "memory");
        __syncthreads();
        if (s + 2 < CNSTEP) conv_load(sb, s + 2, cobase, q0, b, tid);
        mma_stepC(sb + (uint32_t)(s % 3) * CSTG, wm, wn, lane, f);
    }

    int head = (cobase >> 6) + wm;
    int qb = q0 + wn * 32;
    float inv = rsqrtf(1.0f + BN_EPS);
    float av[4][2];
    int hwv[4][2];
    #pragma unroll
    for (int nt = 0; nt < 4; nt++) {
        #pragma unroll
        for (int e = 0; e < 2; e++) {
            int qq = qb + nt * 8 + (lane & 3) * 2 + e;
            int pr = qq / 41, pc = qq - pr * 41;
            bool ok = (pc < 40 && pr < 40);
            int hw = pr * 40 + pc;
            hwv[nt][e] = ok ? hw : -1;
            av[nt][e] = ok ? attn_buf[(size_t)(b * NH + head) * HW + hw] : 0.f;
        }
    }
    #pragma unroll
    for (int mt = 0; mt < 4; mt++) {
        int r0 = cobase + wm * 64 + mt * 16 + (lane >> 2);
        float sc0 = gamma_p[r0] * inv,     bt0 = beta_p[r0];
        float sc8 = gamma_p[r0 + 8] * inv, bt8 = beta_p[r0 + 8];
        #pragma unroll
        for (int nt = 0; nt < 4; nt++) {
            #pragma unroll
            for (int e = 0; e < 2; e++) {
                int hw = hwv[nt][e];
                if (hw >= 0) {
                    out[((size_t)(b * COUT + r0)) * HW + hw]     = (f.acc[mt][nt][e]     * sc0 + bt0) * av[nt][e];
                    out[((size_t)(b * COUT + r0 + 8)) * HW + hw] = (f.acc[mt][nt][e + 2] * sc8 + bt8) * av[nt][e];
                }
            }
        }
    }
}

// ====== embed 1x1 (M=256=all E, N=64 q) + MMA attn: 256 thr, 2 CTAs/SM =====
#define E_BHI  32768
#define ESTG   40960       // A 32K | B 8K
#define ENSTEP 8
#define TSH 264                          // fp16 tile row stride (halves)
#define GSH_OFF (64 * TSH)               // g region offset (halves)
#define ESMEM 81920                      // max(2 stages, tile+g = 76032)

__device__ __forceinline__ void embed_load(uint32_t sb, int s, int q0, int b, int tid) {
    uint32_t st = sb + (uint32_t)(s & 1) * ESTG;
    const char* a_src = (const char*)(we_h + s * 64);
    size_t xoff = ((size_t)b * PBUF + XOFF + q0) * CIN + s * 64;
    const char* b_src = (const char*)(xp_hi + xoff);
    #pragma unroll
    for (int i = 0; i < 8; i++) {        // A: 2048 cp16 (256 rows x 128B)
        int id = tid + i * 256;
        int row = id >> 3, ch = id & 7;
        cp16(st + SW128(row * 128 + ch * 16), a_src + (size_t)row * 1024 + ch * 16);
    }
    #pragma unroll
    for (int i = 0; i < 2; i++) {        // B: 512 cp16 (64 rows x 128B)
        int id = tid + i * 256;
        int row = id >> 3, ch = id & 7;
        cp16(st + E_BHI + SW128(row * 128 + ch * 16), b_src + (size_t)row * 1024 + ch * 16);
    }
    asm volatile("cp.async.commit_group;" ::: "memory");
}

__device__ __forceinline__ void mma_stepE(uint32_t st, int wm, int wn, int lane,
                                          FragC& f) {
    int lr    = lane & 15;
    int ahalf = ((lane >> 4) & 1) * 16;
    int brow  = ((lane >> 4) & 1) * 8 + (lane & 7);
    int bhalf = ((lane >> 3) & 1) * 16;
    uint32_t bh[4][2][4];
    #pragma unroll
    for (int kk = 0; kk < 4; kk++)
        #pragma unroll
        for (int bt = 0; bt < 2; bt++) {
            uint32_t off = SW128((uint32_t)(wn * 32 + bt * 16 + brow) * 128 + kk * 32 + bhalf);
            LDSM_X4(bh[kk][bt], st + E_BHI + off);
        }
    #pragma unroll
    for (int kk = 0; kk < 4; kk++) {
        #pragma unroll
        for (int mt = 0; mt < 4; mt++) {
            uint32_t a[4];
            uint32_t off = SW128((uint32_t)(wm * 64 + mt * 16 + lr) * 128 + kk * 32 + ahalf);
            LDSM_X4(a, st + off);
            #pragma unroll
            for (int nt = 0; nt < 4; nt++) {
                int bt = nt >> 1, pp = (nt & 1) * 2;
                MMA16816(f.acc[mt][nt], a, bh[kk][bt][pp], bh[kk][bt][pp + 1]);
            }
        }
    }
}

__global__ void __launch_bounds__(256, 2)
embed_attn(const float* __restrict__ gamma_e,
           const float* __restrict__ beta_e,
           const float* __restrict__ head_bias) {
    extern __shared__ __align__(1024) char smem[];
    uint32_t sb = smem_u32(smem);
    int tid = threadIdx.x, wid = tid >> 5, lane = tid & 31;
    int q0 = blockIdx.x * 64;
    int b  = blockIdx.z;
    int wm = wid >> 1, wn = wid & 1;      // warp tile 64(E) x 32(q)

    FragC f;
    #pragma unroll
    for (int mt = 0; mt < 4; mt++)
        #pragma unroll
        for (int nt = 0; nt < 4; nt++)
            #pragma unroll
            for (int r = 0; r < 4; r++) f.acc[mt][nt][r] = 0.f;

    embed_load(sb, 0, q0, b, tid);
    for (int s = 0; s < ENSTEP; s++) {
        asm volatile("cp.async.wait_group 0;" ::: "memory");
        __syncthreads();
        if (s + 1 < ENSTEP) embed_load(sb, s + 1, q0, b, tid);
        mma_stepE(sb + (uint32_t)(s & 1) * ESTG, wm, wn, lane, f);
    }
    __syncthreads();   // stage buffers reused below

    // BN + write fp16 tile[q][e] (stride TSH halves)
    __half* tile = reinterpret_cast<__half*>(smem);
    __half* gsm  = tile + GSH_OFF;
    float inv = rsqrtf(1.0f + BN_EPS);
    #pragma unroll
    for (int mt = 0; mt < 4; mt++) {
        int er = wm * 64 + mt * 16 + (lane >> 2);
        float sc0 = gamma_e[er] * inv,     bt0 = beta_e[er];
        float sc8 = gamma_e[er + 8] * inv, bt8 = beta_e[er + 8];
        #pragma unroll
        for (int nt = 0; nt < 4; nt++) {
            int ql = wn * 32 + nt * 8 + (lane & 3) * 2;
            tile[ql * TSH + er]           = __float2half(f.acc[mt][nt][0] * sc0 + bt0);
            tile[(ql + 1) * TSH + er]     = __float2half(f.acc[mt][nt][1] * sc0 + bt0);
            tile[ql * TSH + er + 8]       = __float2half(f.acc[mt][nt][2] * sc8 + bt8);
            tile[(ql + 1) * TSH + er + 8] = __float2half(f.acc[mt][nt][3] * sc8 + bt8);
        }
    }
    // stage g[b] as fp16: gsm[n*TSH + e]
    {
        const float* gsrc = g_buf + (size_t)b * NTOK * EE;
        for (int i = tid; i < NTOK * EE / 4; i += 256) {
            int n = i >> 6, eq = (i & 63) * 4;
            float4 v = reinterpret_cast<const float4*>(gsrc)[i];
            __half h4[4] = {__float2half(v.x), __float2half(v.y),
                            __float2half(v.z), __float2half(v.w)};
            *reinterpret_cast<uint2*>(&gsm[n * TSH + eq]) = *reinterpret_cast<const uint2*>(h4);
        }
    }
    __syncthreads();

    // ---- MMA attention scores: warp = head m, covers all 64 q ----
    int m  = wid;
    uint32_t tb = sb;
    uint32_t gb = sb + GSH_OFF * 2;
    int lr = lane & 15;
    int ah16 = ((lane >> 4) & 1) * 16;
    int brow = ((lane >> 4) & 1) * 8 + (lane & 7);
    int bh16 = ((lane >> 3) & 1) * 16;

    uint32_t a[4][2][4];
    #pragma unroll
    for (int mt = 0; mt < 4; mt++)
        #pragma unroll
        for (int kk = 0; kk < 2; kk++) {
            uint32_t addr = tb + (uint32_t)(mt * 16 + lr) * (TSH * 2)
                          + (m * 32 + kk * 16) * 2 + ah16;
            LDSM_X4(a[mt][kk], addr);
        }

    float rmax[4][2];
    #pragma unroll
    for (int mt = 0; mt < 4; mt++) { rmax[mt][0] = -3.4e38f; rmax[mt][1] = -3.4e38f; }

    #pragma unroll
    for (int nt16 = 0; nt16 < 5; nt16++) {
        uint32_t b0[4], b1[4];
        uint32_t baddr = gb + (uint32_t)(nt16 * 16 + brow) * (TSH * 2) + m * 32 * 2 + bh16;
        LDSM_X4(b0, baddr);
        LDSM_X4(b1, baddr + 32);
        #pragma unroll
        for (int sub = 0; sub < 2; sub++) {
            #pragma unroll
            for (int mt = 0; mt < 4; mt++) {
                float acc[4] = {0.f, 0.f, 0.f, 0.f};
                MMA16816(acc, a[mt][0], b0[sub * 2], b0[sub * 2 + 1]);
                MMA16816(acc, a[mt][1], b1[sub * 2], b1[sub * 2 + 1]);
                rmax[mt][0] = fmaxf(rmax[mt][0], fmaxf(acc[0], acc[1]));
                rmax[mt][1] = fmaxf(rmax[mt][1], fmaxf(acc[2], acc[3]));
            }
        }
    }

    float hb = head_bias[m];
    #pragma unroll
    for (int mt = 0; mt < 4; mt++) {
        #pragma unroll
        for (int r01 = 0; r01 < 2; r01++) {
            float v = rmax[mt][r01];
            v = fmaxf(v, __shfl_xor_sync(0xFFFFFFFFu, v, 1));
            v = fmaxf(v, __shfl_xor_sync(0xFFFFFFFFu, v, 2));
            if ((lane & 3) == 0) {
                int qq = q0 + mt * 16 + (lane >> 2) + r01 * 8;
                int pr = qq / 41, pc = qq - pr * 41;
                if (pc < 40 && pr < 40) {
                    float aa = v * 0.17677669529663687f + hb;
                    float s = 1.0f / (1.0f + __expf(-aa));
                    attn_buf[(size_t)(b * NH + m) * HW + pr * 40 + pc] = s;
                }
            }
        }
    }
}

extern "C" void kernel_launch(void* const* d_in, const int* in_sizes, int n_in,
                              void* d_out, int out_size) {
    const float* x         = (const float*)d_in[0];
    const float* guide     = (const float*)d_in[1];
    const float* We        = (const float*)d_in[2];
    const float* gamma_e   = (const float*)d_in[3];
    const float* beta_e    = (const float*)d_in[4];
    const float* Wg        = (const float*)d_in[5];
    const float* bg        = (const float*)d_in[6];
    const float* head_bias = (const float*)d_in[7];
    const float* Wp        = (const float*)d_in[8];
    const float* gamma_p   = (const float*)d_in[9];
    const float* beta_p    = (const float*)d_in[10];
    float* out = (float*)d_out;

    xprep<<<dim3(40, 8, 16), 256>>>(x);
    prep_wg<<<COUT + EE + 320, 256>>>(Wp, We, guide, Wg, bg);
    cudaFuncSetAttribute(embed_attn, cudaFuncAttributeMaxDynamicSharedMemorySize, ESMEM);
    embed_attn<<<dim3(26, 1, 16), 256, ESMEM>>>(gamma_e, beta_e, head_bias);
    cudaFuncSetAttribute(conv_mma, cudaFuncAttributeMaxDynamicSharedMemorySize, CSMEM);
    conv_mma<<<dim3(13, 4, 16), 256, CSMEM>>>(gamma_p, beta_p, out);
}